// round 15
// baseline (speedup 1.0000x reference)
#include <cuda_runtime.h>
#include <cuda_bf16.h>
#include <cuda_fp16.h>
#include <math.h>
#include <stdint.h>

// ---------------- problem constants ----------------
#define NB       512
#define PP       64
#define NN       (NB*PP)      // 32768
#define FF       128
#define HH       256
#define KSORT    30
#define LOUT     27
#define MCONV    (NB*LOUT)    // 13824

// ---------------- static scratch ----------------
__device__ __align__(16) float g_A  [NB*PP*PP];
__device__ __align__(16) float g_H  [NN*HH];      // fp32 activations (sort keys)
__device__ __align__(16) float g_HL [NN*HH];
__device__ __align__(16) float g_HR [NN*HH];
__device__ __align__(16) float g_z1 [NB*HH];
// bf16 3-plane activations ping/pong
__device__ __align__(16) __nv_bfloat16 g_a0[NN*HH], g_a1[NN*HH], g_a2[NN*HH];
__device__ __align__(16) __nv_bfloat16 g_b0[NN*HH], g_b1[NN*HH], g_b2[NN*HH];
// bf16 sage weight planes [8 mats][256][K]
__device__ __align__(16) __nv_bfloat16 g_w0[8*HH*HH], g_w1[8*HH*HH], g_w2[8*HH*HH];
// conv path (bf16 2-plane)
__device__ __align__(16) __nv_bfloat16 g_t0[NB*KSORT*HH], g_t1[NB*KSORT*HH];
__device__ __align__(16) __nv_bfloat16 g_c0[HH*1024],     g_c1[HH*1024];
// conv output as bf16 split-2 planes
__device__ __align__(16) __nv_bfloat16 g_y0[MCONV*HH], g_y1[MCONV*HH];
// lin1 weight planes [ts][n][o]
__device__ __align__(16) __nv_bfloat16 g_l0[LOUT*HH*HH], g_l1[LOUT*HH*HH];

// ---------------- helpers ----------------
__device__ __forceinline__ uint32_t smem_u32(const void* p) {
    uint32_t a;
    asm("{ .reg .u64 t; cvta.to.shared.u64 t, %1; cvt.u32.u64 %0, t; }" : "=r"(a) : "l"(p));
    return a;
}
__device__ __forceinline__ void cpasync16(uint32_t dst, const void* src) {
    asm volatile("cp.async.cg.shared.global [%0], [%1], 16;" :: "r"(dst), "l"(src));
}
__device__ __forceinline__ void ldsm4(uint32_t* r, uint32_t addr) {
    asm volatile("ldmatrix.sync.aligned.m8n8.x4.shared.b16 {%0,%1,%2,%3}, [%4];"
        : "=r"(r[0]), "=r"(r[1]), "=r"(r[2]), "=r"(r[3]) : "r"(addr));
}
__device__ __forceinline__ void mma16bf(float* d, uint32_t a0, uint32_t a1,
                                        uint32_t a2, uint32_t a3,
                                        uint32_t b0, uint32_t b1) {
    asm volatile(
        "mma.sync.aligned.m16n8k16.row.col.f32.bf16.bf16.f32 "
        "{%0,%1,%2,%3}, {%4,%5,%6,%7}, {%8,%9}, {%0,%1,%2,%3};"
        : "+f"(d[0]), "+f"(d[1]), "+f"(d[2]), "+f"(d[3])
        : "r"(a0), "r"(a1), "r"(a2), "r"(a3), "r"(b0), "r"(b1));
}
__device__ __forceinline__ void mma16bfa(float* d, const uint32_t* a,
                                         uint32_t b0, uint32_t b1) {
    asm volatile(
        "mma.sync.aligned.m16n8k16.row.col.f32.bf16.bf16.f32 "
        "{%0,%1,%2,%3}, {%4,%5,%6,%7}, {%8,%9}, {%0,%1,%2,%3};"
        : "+f"(d[0]), "+f"(d[1]), "+f"(d[2]), "+f"(d[3])
        : "r"(a[0]), "r"(a[1]), "r"(a[2]), "r"(a[3]), "r"(b0), "r"(b1));
}
struct BF3 { __nv_bfloat16 x, y, z; };
__device__ __forceinline__ BF3 bf16_split3(float v) {
    BF3 r;
    r.x = __float2bfloat16(v);
    float r1 = v - __bfloat162float(r.x);
    r.y = __float2bfloat16(r1);
    float r2 = r1 - __bfloat162float(r.y);
    r.z = __float2bfloat16(r2);
    return r;
}
__device__ __forceinline__ __nv_bfloat162 bf2_split(float v) {
    __nv_bfloat16 h0 = __float2bfloat16(v);
    __nv_bfloat16 h1 = __float2bfloat16(v - __bfloat162float(h0));
    __nv_bfloat162 r; r.x = h0; r.y = h1; return r;
}

// ===== SAGE GEMM: bf16 3-plane 6-product split-acc (R7-exact chains) ========
// Per-accumulator MMA order per (chunk asc, s asc):
//   hi += a0b0 ; lo += a0b1, a1b0, a1b1, a0b2, a2b0   — exactly round-7's,
// which passed. Pass-split across the 4 independent accumulators per jp.
#define GPROW_B   80
#define GA_PLANE  (128*GPROW_B)             // 10240
#define GB_PLANE  (64*GPROW_B)              // 5120
#define GSTAGE    (3*GA_PLANE + 3*GB_PLANE) // 46080
#define GSMZ      (2*GSTAGE)                // 92160

__global__ __launch_bounds__(256, 2) void gemm_sage_tc(
    const __nv_bfloat16* __restrict__ A0, const __nv_bfloat16* __restrict__ A1,
    const __nv_bfloat16* __restrict__ A2,
    const __nv_bfloat16* __restrict__ L0, const __nv_bfloat16* __restrict__ L1,
    const __nv_bfloat16* __restrict__ L2,
    const __nv_bfloat16* __restrict__ R0, const __nv_bfloat16* __restrict__ R1,
    const __nv_bfloat16* __restrict__ R2,
    float* __restrict__ Cl, float* __restrict__ Cr, int K)
{
    extern __shared__ char smem[];
    const int t    = threadIdx.x;
    const int lane = t & 31;
    const int wid  = t >> 5;
    const int wm   = wid & 3;
    const int wn   = wid >> 2;
    const int m0   = blockIdx.y * 128;
    const int sel  = blockIdx.x >> 2;
    const int n0   = (blockIdx.x & 3) * 64;
    const int lr   = lane >> 2;
    const int lc   = lane & 3;
    const int nch  = K >> 5;

    const __nv_bfloat16* W0 = sel ? R0 : L0;
    const __nv_bfloat16* W1 = sel ? R1 : L1;
    const __nv_bfloat16* W2 = sel ? R2 : L2;
    float* C = sel ? Cr : Cl;

    uint32_t sbase = smem_u32(smem);

    const int l15    = lane & 15;
    const int koff_a = (lane >> 4) * 16;
    const int brow_l = ((lane >> 4) << 3) + (lane & 7);
    const int koff_b = ((lane >> 3) & 1) * 16;

    auto ld_stage = [&](int stage, int c) {
        uint32_t sb = sbase + stage * GSTAGE;
        int kt = c << 5;
        #pragma unroll
        for (int i = 0; i < 9; i++) {
            int idx = t + i * 256;              // 0..2303
            if (idx < 1536) {                   // A: 3 planes x 128 rows x 4 quads
                int pl = idx >> 9, rem = idx & 511;
                int row = rem >> 2, q = rem & 3;
                const __nv_bfloat16* P = (pl == 0) ? A0 : ((pl == 1) ? A1 : A2);
                cpasync16(sb + pl * GA_PLANE + row * GPROW_B + q * 16,
                          P + (size_t)(m0 + row) * K + kt + q * 8);
            } else {                            // B: 3 planes x 64 rows x 4 quads
                int idx2 = idx - 1536;
                int pl = idx2 >> 8, rem = idx2 & 255;
                int row = rem >> 2, q = rem & 3;
                const __nv_bfloat16* P = (pl == 0) ? W0 : ((pl == 1) ? W1 : W2);
                cpasync16(sb + 3 * GA_PLANE + pl * GB_PLANE + row * GPROW_B + q * 16,
                          P + (size_t)(n0 + row) * K + kt + q * 8);
            }
        }
        asm volatile("cp.async.commit_group;" ::: "memory");
    };

    float acc_hi[2][4][4], acc_lo[2][4][4];
    #pragma unroll
    for (int m = 0; m < 2; m++)
        #pragma unroll
        for (int j = 0; j < 4; j++)
            #pragma unroll
            for (int q = 0; q < 4; q++) { acc_hi[m][j][q] = 0.f; acc_lo[m][j][q] = 0.f; }

    ld_stage(0, 0);
    if (nch > 1) ld_stage(1, 1);

    for (int c = 0; c < nch; c++) {
        if (c + 1 < nch) asm volatile("cp.async.wait_group 1;" ::: "memory");
        else             asm volatile("cp.async.wait_group 0;" ::: "memory");
        __syncthreads();

        uint32_t sb = sbase + (c & 1) * GSTAGE;

        #pragma unroll
        for (int s = 0; s < 2; s++) {
            uint32_t a0f[2][4], a1f[2][4], a2f[2][4];
            #pragma unroll
            for (int m = 0; m < 2; m++) {
                uint32_t rowb = (uint32_t)((wm * 32 + m * 16 + l15) * GPROW_B
                                           + s * 32 + koff_a);
                ldsm4(a0f[m], sb + rowb);
                ldsm4(a1f[m], sb + GA_PLANE + rowb);
                ldsm4(a2f[m], sb + 2 * GA_PLANE + rowb);
            }
            #pragma unroll
            for (int jp = 0; jp < 2; jp++) {
                uint32_t nrow = sb + 3 * GA_PLANE
                    + (uint32_t)((wn * 32 + jp * 16 + brow_l) * GPROW_B
                                 + s * 32 + koff_b);
                uint32_t b0[4], b1[4], b2[4];
                ldsm4(b0, nrow);
                ldsm4(b1, nrow + GB_PLANE);
                ldsm4(b2, nrow + 2 * GB_PLANE);
                // R7 per-acc chain, pass-split across 4 independent accumulators
                #pragma unroll
                for (int jj = 0; jj < 2; jj++)
                    #pragma unroll
                    for (int m = 0; m < 2; m++)
                        mma16bfa(acc_hi[m][jp*2+jj], a0f[m], b0[2*jj], b0[2*jj+1]);
                #pragma unroll
                for (int jj = 0; jj < 2; jj++)
                    #pragma unroll
                    for (int m = 0; m < 2; m++)
                        mma16bfa(acc_lo[m][jp*2+jj], a0f[m], b1[2*jj], b1[2*jj+1]);
                #pragma unroll
                for (int jj = 0; jj < 2; jj++)
                    #pragma unroll
                    for (int m = 0; m < 2; m++)
                        mma16bfa(acc_lo[m][jp*2+jj], a1f[m], b0[2*jj], b0[2*jj+1]);
                #pragma unroll
                for (int jj = 0; jj < 2; jj++)
                    #pragma unroll
                    for (int m = 0; m < 2; m++)
                        mma16bfa(acc_lo[m][jp*2+jj], a1f[m], b1[2*jj], b1[2*jj+1]);
                #pragma unroll
                for (int jj = 0; jj < 2; jj++)
                    #pragma unroll
                    for (int m = 0; m < 2; m++)
                        mma16bfa(acc_lo[m][jp*2+jj], a0f[m], b2[2*jj], b2[2*jj+1]);
                #pragma unroll
                for (int jj = 0; jj < 2; jj++)
                    #pragma unroll
                    for (int m = 0; m < 2; m++)
                        mma16bfa(acc_lo[m][jp*2+jj], a2f[m], b0[2*jj], b0[2*jj+1]);
            }
        }
        if (c + 2 < nch) {
            __syncthreads();
            ld_stage(c & 1, c + 2);
        }
    }

    #pragma unroll
    for (int m = 0; m < 2; m++) {
        int row = m0 + wm * 32 + m * 16 + lr;
        #pragma unroll
        for (int j = 0; j < 4; j++) {
            int col = n0 + wn * 32 + j * 8 + 2 * lc;
            float2 v0 = make_float2(acc_hi[m][j][0] + acc_lo[m][j][0],
                                    acc_hi[m][j][1] + acc_lo[m][j][1]);
            float2 v1 = make_float2(acc_hi[m][j][2] + acc_lo[m][j][2],
                                    acc_hi[m][j][3] + acc_lo[m][j][3]);
            *(float2*)(C + (size_t)row * 256 + col)       = v0;
            *(float2*)(C + (size_t)(row + 8) * 256 + col) = v1;
        }
    }
}

// ---------------- prep kernels ----------------
__global__ void zero_f(float* p, int n) {
    int i = blockIdx.x * 256 + threadIdx.x;
    if (i < n) p[i] = 0.f;
}

__global__ void nan_split3(const float* __restrict__ x,
                           __nv_bfloat16* __restrict__ p0, __nv_bfloat16* __restrict__ p1,
                           __nv_bfloat16* __restrict__ p2, int n) {
    int i = blockIdx.x * 256 + threadIdx.x;
    if (i >= n) return;
    float v = x[i]; v = isnan(v) ? 0.f : v;
    BF3 s = bf16_split3(v);
    p0[i] = s.x; p1[i] = s.y; p2[i] = s.z;
}

__global__ void build_adj(const int* __restrict__ src, const int* __restrict__ dst,
                          int E, float* __restrict__ A) {
    int e = blockIdx.x * 256 + threadIdx.x;
    if (e >= E) return;
    int s = src[e], d = dst[e];
    int g = d >> 6;
    atomicAdd(&A[((size_t)g << 12) + ((size_t)(d & 63) << 6) + (s & 63)], 1.0f);
}

__global__ void norm_adj(float* __restrict__ A) {
    int row  = blockIdx.x * 8 + (threadIdx.x >> 5);
    int lane = threadIdx.x & 31;
    float* rp = A + (size_t)row * 64;
    float v0 = rp[lane], v1 = rp[lane + 32];
    float s = v0 + v1;
    #pragma unroll
    for (int o = 16; o > 0; o >>= 1) s += __shfl_xor_sync(0xffffffffu, s, o);
    float inv = 1.f / fmaxf(s, 1.f);
    rp[lane] = v0 * inv; rp[lane + 32] = v1 * inv;
}

// ===== merged weight-split prep =============================================
#define W1_ELEMS   (LOUT*256*256)            // 1769472
#define CV_ELEMS   (256*1024)                // 262144
#define SG_ELEMS   (2*(128+256+256+256)*256) // 458752
#define PREP_TOTAL (W1_ELEMS + CV_ELEMS + SG_ELEMS)

__global__ void prep_split(
    const float* __restrict__ wl0, const float* __restrict__ wr0,
    const float* __restrict__ wl1, const float* __restrict__ wr1,
    const float* __restrict__ wl2, const float* __restrict__ wr2,
    const float* __restrict__ wl3, const float* __restrict__ wr3,
    const float* __restrict__ convw, const float* __restrict__ l1w,
    __nv_bfloat16* __restrict__ pw0, __nv_bfloat16* __restrict__ pw1,
    __nv_bfloat16* __restrict__ pw2,
    __nv_bfloat16* __restrict__ pc0, __nv_bfloat16* __restrict__ pc1,
    __nv_bfloat16* __restrict__ pl0, __nv_bfloat16* __restrict__ pl1)
{
    int idx = blockIdx.x * 256 + threadIdx.x;
    if (idx >= PREP_TOTAL) return;
    if (idx < W1_ELEMS) {
        int ts = idx >> 16;
        int rem = idx & 65535;
        int n = rem >> 8, o = rem & 255;
        float v = l1w[((size_t)(o * LOUT + ts)) * 256 + n];
        __nv_bfloat16 h0 = __float2bfloat16(v);
        pl0[idx] = h0;
        pl1[idx] = __float2bfloat16(v - __bfloat162float(h0));
    } else if (idx < W1_ELEMS + CV_ELEMS) {
        int i2 = idx - W1_ELEMS;
        int o = i2 >> 10, k = i2 & 1023;
        int s = k >> 8, i = k & 255;
        float v = convw[((size_t)(o * 256 + i)) * 4 + s];
        __nv_bfloat16 h0 = __float2bfloat16(v);
        pc0[i2] = h0;
        pc1[i2] = __float2bfloat16(v - __bfloat162float(h0));
    } else {
        // sage planes: transpose+split3 [K][256] -> [256][K] bf16 triple
        int i2 = idx - (W1_ELEMS + CV_ELEMS);
        int mat, off, K;
        if (i2 < 65536) { mat = i2 >> 15; off = i2 & 32767; K = 128; }
        else {
            int j = i2 - 65536;
            mat = 2 + (j >> 16); off = j & 65535; K = 256;
        }
        const float* src;
        switch (mat) {
            case 0: src = wl0; break;
            case 1: src = wr0; break;
            case 2: src = wl1; break;
            case 3: src = wr1; break;
            case 4: src = wl2; break;
            case 5: src = wr2; break;
            case 6: src = wl3; break;
            default: src = wr3; break;
        }
        int k = off >> 8, n = off & 255;
        BF3 s = bf16_split3(src[off]);
        size_t d = (size_t)mat * (HH * HH) + (size_t)n * K + k;
        pw0[d] = s.x; pw1[d] = s.y; pw2[d] = s.z;
    }
}

// ------------- SAGE combine (R1-exact chains) + bf16 split-3 emit -----------
__global__ __launch_bounds__(256) void sage_combine(
    const float* __restrict__ HL, const float* __restrict__ HR,
    const float* __restrict__ bias, float* __restrict__ Hout,
    __nv_bfloat16* __restrict__ p0, __nv_bfloat16* __restrict__ p1,
    __nv_bfloat16* __restrict__ p2,
    const float* __restrict__ Aadj, int emit_h, int emit_planes)
{
    __shared__ float As[64][64];
    __shared__ float HLs[64][128];
    int g = blockIdx.x, t = threadIdx.x;
    const float* Ag = Aadj + ((size_t)g << 12);

    #pragma unroll
    for (int h = 0; h < 4; h++) {
        int idx = t + h * 256;
        int n = idx >> 4, k4 = (idx & 15) * 4;
        float4 v = *reinterpret_cast<const float4*>(Ag + (size_t)n * 64 + k4);
        As[k4 + 0][n] = v.x; As[k4 + 1][n] = v.y;
        As[k4 + 2][n] = v.z; As[k4 + 3][n] = v.w;
    }

    int ngrp = t >> 4;
    int cgrp = t & 15;

    for (int ch = 0; ch < 2; ch++) {
        __syncthreads();
        #pragma unroll
        for (int h = 0; h < 8; h++) {
            int idx = t + h * 256;
            int k = idx >> 5, c4 = (idx & 31) * 4;
            *reinterpret_cast<float4*>(&HLs[k][c4]) =
                *reinterpret_cast<const float4*>(HL + ((size_t)(g * 64 + k)) * HH + ch * 128 + c4);
        }
        __syncthreads();

        float acc[4][8];
        #pragma unroll
        for (int i = 0; i < 4; i++)
            #pragma unroll
            for (int j = 0; j < 8; j++) acc[i][j] = 0.f;

        #pragma unroll 4
        for (int k = 0; k < 64; k++) {
            float a[4], b[8];
            *reinterpret_cast<float4*>(&a[0]) = *reinterpret_cast<const float4*>(&As[k][ngrp * 4]);
            *reinterpret_cast<float4*>(&b[0]) = *reinterpret_cast<const float4*>(&HLs[k][cgrp * 8]);
            *reinterpret_cast<float4*>(&b[4]) = *reinterpret_cast<const float4*>(&HLs[k][cgrp * 8 + 4]);
            #pragma unroll
            for (int i = 0; i < 4; i++)
                #pragma unroll
                for (int j = 0; j < 8; j++) acc[i][j] += a[i] * b[j];
        }
        #pragma unroll
        for (int i = 0; i < 4; i++) {
            int n = ngrp * 4 + i;
            size_t base = ((size_t)(g * 64 + n)) * HH + ch * 128 + cgrp * 8;
            #pragma unroll
            for (int j = 0; j < 8; j++) {
                float v = acc[i][j] + bias[ch * 128 + cgrp * 8 + j] + HR[base + j];
                float h = fmaxf(v, 0.f);
                if (emit_h) Hout[base + j] = h;
                if (emit_planes) {
                    BF3 s = bf16_split3(h);
                    p0[base + j] = s.x; p1[base + j] = s.y; p2[base + j] = s.z;
                }
            }
        }
    }
}

// ------------- SortPool (verbatim) -------------------------------------------
__global__ __launch_bounds__(256) void sort_topk2(
    const float* __restrict__ H,
    __nv_bfloat16* __restrict__ t0, __nv_bfloat16* __restrict__ t1)
{
    int g = blockIdx.x, t = threadIdx.x;
    __shared__ float keys[64];
    __shared__ int   sel[KSORT];
    if (t < 64) keys[t] = H[((size_t)(g * 64 + t)) * HH + 255];
    __syncthreads();
    if (t < 64) {
        float kv = keys[t];
        int r = 0;
        #pragma unroll
        for (int m = 0; m < 64; m++) {
            float km = keys[m];
            r += (km > kv) || (km == kv && m < t);
        }
        if (r < KSORT) sel[r] = t;
    }
    __syncthreads();
    for (int idx = t; idx < KSORT * HH; idx += 256) {
        int r = idx >> 8, c = idx & 255;
        float v = H[((size_t)(g * 64 + sel[r])) * HH + c];
        __nv_bfloat16 h0 = __float2bfloat16(v);
        size_t d = (size_t)g * KSORT * HH + idx;
        t0[d] = h0;
        t1[d] = __float2bfloat16(v - __bfloat162float(h0));
    }
}

// ============ conv1d TC GEMM (verbatim R14) ==================================
#define CPROW_B   80
#define CPLANE_B  (128*CPROW_B)
#define CSTAGE_B  (4*CPLANE_B)
#define CSMZ      (2*CSTAGE_B)

__global__ __launch_bounds__(256) void conv_tc(
    const __nv_bfloat16* __restrict__ T0, const __nv_bfloat16* __restrict__ T1,
    const __nv_bfloat16* __restrict__ W0, const __nv_bfloat16* __restrict__ W1,
    __nv_bfloat16* __restrict__ Y0, __nv_bfloat16* __restrict__ Y1,
    const float* __restrict__ bias)
{
    extern __shared__ char smem[];
    const int t    = threadIdx.x;
    const int lane = t & 31;
    const int wid  = t >> 5;
    const int wm   = wid & 3;
    const int wn   = wid >> 2;
    const int m0   = blockIdx.y * 128;
    const int n0   = blockIdx.x * 128;
    const int lr   = lane >> 2;
    const int lc   = lane & 3;
    const int nch  = 32;

    uint32_t sbase = smem_u32(smem);

    auto ld_stage = [&](int stage, int c) {
        uint32_t sb = sbase + stage * CSTAGE_B;
        int kt = c << 5;
        int sp = kt >> 8, ko = kt & 255;
        #pragma unroll
        for (int i = 0; i < 8; i++) {
            int idx = t + i * 256;
            int pl  = idx >> 9;
            int rem = idx & 511;
            int row = rem >> 2, q = rem & 3;
            uint32_t dst = sb + pl * CPLANE_B + row * CPROW_B + q * 16;
            const __nv_bfloat16* src;
            if (pl < 2) {
                const __nv_bfloat16* P = (pl == 0) ? T0 : T1;
                int m = m0 + row;
                int g = m / 27, tp = m - g * 27;
                src = P + (size_t)((g * 30 + tp + sp) * 256 + ko) + q * 8;
            } else {
                const __nv_bfloat16* P = (pl == 2) ? W0 : W1;
                src = P + (size_t)(n0 + row) * 1024 + kt + q * 8;
            }
            cpasync16(dst, src);
        }
        asm volatile("cp.async.commit_group;" ::: "memory");
    };

    float acc[2][8][4];
    #pragma unroll
    for (int m = 0; m < 2; m++)
        #pragma unroll
        for (int j = 0; j < 8; j++)
            #pragma unroll
            for (int q = 0; q < 4; q++) acc[m][j][q] = 0.f;

    ld_stage(0, 0);
    ld_stage(1, 1);

    for (int c = 0; c < nch; c++) {
        if (c + 1 < nch) asm volatile("cp.async.wait_group 1;" ::: "memory");
        else             asm volatile("cp.async.wait_group 0;" ::: "memory");
        __syncthreads();

        const char* sb = smem + (c & 1) * CSTAGE_B;

        #pragma unroll
        for (int s = 0; s < 2; s++) {
            int kc = s * 32 + lc * 4;
            uint32_t A0f[2][4], A1f[2][4];
            #pragma unroll
            for (int m = 0; m < 2; m++) {
                int r0 = (wm * 32 + m * 16 + lr) * CPROW_B;
                int r1 = r0 + 8 * CPROW_B;
                A0f[m][0] = *(const uint32_t*)(sb + r0 + kc);
                A0f[m][1] = *(const uint32_t*)(sb + r1 + kc);
                A0f[m][2] = *(const uint32_t*)(sb + r0 + kc + 16);
                A0f[m][3] = *(const uint32_t*)(sb + r1 + kc + 16);
                A1f[m][0] = *(const uint32_t*)(sb + CPLANE_B + r0 + kc);
                A1f[m][1] = *(const uint32_t*)(sb + CPLANE_B + r1 + kc);
                A1f[m][2] = *(const uint32_t*)(sb + CPLANE_B + r0 + kc + 16);
                A1f[m][3] = *(const uint32_t*)(sb + CPLANE_B + r1 + kc + 16);
            }
            #pragma unroll
            for (int j = 0; j < 8; j++) {
                int nr = (wn * 64 + j * 8 + lr) * CPROW_B;
                uint32_t b00 = *(const uint32_t*)(sb + 2*CPLANE_B + nr + kc);
                uint32_t b01 = *(const uint32_t*)(sb + 2*CPLANE_B + nr + kc + 16);
                uint32_t b10 = *(const uint32_t*)(sb + 3*CPLANE_B + nr + kc);
                uint32_t b11 = *(const uint32_t*)(sb + 3*CPLANE_B + nr + kc + 16);
                #pragma unroll
                for (int m = 0; m < 2; m++)
                    mma16bf(acc[m][j], A0f[m][0], A0f[m][1], A0f[m][2], A0f[m][3], b00, b01);
                #pragma unroll
                for (int m = 0; m < 2; m++)
                    mma16bf(acc[m][j], A0f[m][0], A0f[m][1], A0f[m][2], A0f[m][3], b10, b11);
                #pragma unroll
                for (int m = 0; m < 2; m++)
                    mma16bf(acc[m][j], A1f[m][0], A1f[m][1], A1f[m][2], A1f[m][3], b00, b01);
            }
        }
        if (c + 2 < nch) {
            __syncthreads();
            ld_stage(c & 1, c + 2);
        }
    }

    #pragma unroll
    for (int m = 0; m < 2; m++) {
        int row = m0 + wm * 32 + m * 16 + lr;
        #pragma unroll
        for (int j = 0; j < 8; j++) {
            int col = n0 + wn * 64 + j * 8 + 2 * lc;
            float b0 = bias[col], b1 = bias[col + 1];
            float y00 = fmaxf(acc[m][j][0] + b0, 0.f);
            float y01 = fmaxf(acc[m][j][1] + b1, 0.f);
            float y10 = fmaxf(acc[m][j][2] + b0, 0.f);
            float y11 = fmaxf(acc[m][j][3] + b1, 0.f);
            __nv_bfloat162 s00 = bf2_split(y00), s01 = bf2_split(y01);
            __nv_bfloat162 s10 = bf2_split(y10), s11 = bf2_split(y11);
            size_t o0 = (size_t)row * 256 + col;
            size_t o1 = (size_t)(row + 8) * 256 + col;
            __nv_bfloat162 p;
            p.x = s00.x; p.y = s01.x; *(__nv_bfloat162*)(Y0 + o0) = p;
            p.x = s00.y; p.y = s01.y; *(__nv_bfloat162*)(Y1 + o0) = p;
            p.x = s10.x; p.y = s11.x; *(__nv_bfloat162*)(Y0 + o1) = p;
            p.x = s10.y; p.y = s11.y; *(__nv_bfloat162*)(Y1 + o1) = p;
        }
    }
}

// ============ lin1 TC GEMM (verbatim R14) ====================================
__global__ __launch_bounds__(256) void lin1_tc(
    const __nv_bfloat16* __restrict__ Y0, const __nv_bfloat16* __restrict__ Y1,
    const __nv_bfloat16* __restrict__ P0, const __nv_bfloat16* __restrict__ P1,
    float* __restrict__ Z)
{
    extern __shared__ char smem[];
    const int t    = threadIdx.x;
    const int lane = t & 31;
    const int wid  = t >> 5;
    const int wm   = wid & 3;
    const int wn   = wid >> 2;
    const int m0   = blockIdx.y * 128;
    const int n0   = blockIdx.x * 128;
    const int ts   = blockIdx.z;
    const int lr   = lane >> 2;
    const int lc   = lane & 3;
    const int nch  = 8;

    uint32_t sbase = smem_u32(smem);

    auto ld_stage = [&](int stage, int c) {
        uint32_t sb = sbase + stage * CSTAGE_B;
        int kt = c << 5;
        #pragma unroll
        for (int i = 0; i < 8; i++) {
            int idx = t + i * 256;
            int pl  = idx >> 9;
            int rem = idx & 511;
            int row = rem >> 2, q = rem & 3;
            uint32_t dst = sb + pl * CPLANE_B + row * CPROW_B + q * 16;
            const __nv_bfloat16* src;
            if (pl < 2) {
                const __nv_bfloat16* P = (pl == 0) ? Y0 : Y1;
                src = P + ((size_t)((m0 + row) * LOUT + ts)) * 256 + kt + q * 8;
            } else {
                const __nv_bfloat16* P = (pl == 2) ? P0 : P1;
                src = P + ((size_t)(ts * 256 + n0 + row)) * 256 + kt + q * 8;
            }
            cpasync16(dst, src);
        }
        asm volatile("cp.async.commit_group;" ::: "memory");
    };

    float acc[2][8][4];
    #pragma unroll
    for (int m = 0; m < 2; m++)
        #pragma unroll
        for (int j = 0; j < 8; j++)
            #pragma unroll
            for (int q = 0; q < 4; q++) acc[m][j][q] = 0.f;

    ld_stage(0, 0);
    ld_stage(1, 1);

    for (int c = 0; c < nch; c++) {
        if (c + 1 < nch) asm volatile("cp.async.wait_group 1;" ::: "memory");
        else             asm volatile("cp.async.wait_group 0;" ::: "memory");
        __syncthreads();

        const char* sb = smem + (c & 1) * CSTAGE_B;

        #pragma unroll
        for (int s = 0; s < 2; s++) {
            int kc = s * 32 + lc * 4;
            uint32_t A0f[2][4], A1f[2][4];
            #pragma unroll
            for (int m = 0; m < 2; m++) {
                int r0 = (wm * 32 + m * 16 + lr) * CPROW_B;
                int r1 = r0 + 8 * CPROW_B;
                A0f[m][0] = *(const uint32_t*)(sb + r0 + kc);
                A0f[m][1] = *(const uint32_t*)(sb + r1 + kc);
                A0f[m][2] = *(const uint32_t*)(sb + r0 + kc + 16);
                A0f[m][3] = *(const uint32_t*)(sb + r1 + kc + 16);
                A1f[m][0] = *(const uint32_t*)(sb + CPLANE_B + r0 + kc);
                A1f[m][1] = *(const uint32_t*)(sb + CPLANE_B + r1 + kc);
                A1f[m][2] = *(const uint32_t*)(sb + CPLANE_B + r0 + kc + 16);
                A1f[m][3] = *(const uint32_t*)(sb + CPLANE_B + r1 + kc + 16);
            }
            #pragma unroll
            for (int j = 0; j < 8; j++) {
                int nr = (wn * 64 + j * 8 + lr) * CPROW_B;
                uint32_t b00 = *(const uint32_t*)(sb + 2*CPLANE_B + nr + kc);
                uint32_t b01 = *(const uint32_t*)(sb + 2*CPLANE_B + nr + kc + 16);
                uint32_t b10 = *(const uint32_t*)(sb + 3*CPLANE_B + nr + kc);
                uint32_t b11 = *(const uint32_t*)(sb + 3*CPLANE_B + nr + kc + 16);
                #pragma unroll
                for (int m = 0; m < 2; m++)
                    mma16bf(acc[m][j], A0f[m][0], A0f[m][1], A0f[m][2], A0f[m][3], b00, b01);
                #pragma unroll
                for (int m = 0; m < 2; m++)
                    mma16bf(acc[m][j], A0f[m][0], A0f[m][1], A0f[m][2], A0f[m][3], b10, b11);
                #pragma unroll
                for (int m = 0; m < 2; m++)
                    mma16bf(acc[m][j], A1f[m][0], A1f[m][1], A1f[m][2], A1f[m][3], b00, b01);
            }
        }
        if (c + 2 < nch) {
            __syncthreads();
            ld_stage(c & 1, c + 2);
        }
    }

    #pragma unroll
    for (int m = 0; m < 2; m++) {
        int g = m0 + wm * 32 + m * 16 + lr;
        #pragma unroll
        for (int j = 0; j < 8; j++) {
            int col = n0 + wn * 64 + j * 8 + 2 * lc;
            atomicAdd(&Z[(size_t)g * 256 + col],           acc[m][j][0]);
            atomicAdd(&Z[(size_t)g * 256 + col + 1],       acc[m][j][1]);
            atomicAdd(&Z[(size_t)(g + 8) * 256 + col],     acc[m][j][2]);
            atomicAdd(&Z[(size_t)(g + 8) * 256 + col + 1], acc[m][j][3]);
        }
    }
}

// ------------- final MLP (verbatim) ------------------------------------------
__global__ __launch_bounds__(256) void mlp_kernel(
    const float* __restrict__ z1acc, const float* __restrict__ b1,
    const float* __restrict__ W2,   const float* __restrict__ b2,
    const float* __restrict__ W3,   const float* __restrict__ b3,
    float* __restrict__ out)
{
    int g = blockIdx.x, t = threadIdx.x;
    __shared__ float s1[256];
    __shared__ float s2[128];
    s1[t] = fmaxf(z1acc[(size_t)g * 256 + t] + b1[t], 0.f);
    __syncthreads();
    if (t < 128) {
        float acc = b2[t];
        #pragma unroll 8
        for (int k = 0; k < 256; k++) acc += s1[k] * W2[(size_t)k * 128 + t];
        s2[t] = fmaxf(acc, 0.f);
    }
    __syncthreads();
    if (t < 10) {
        float acc = b3[t];
        #pragma unroll
        for (int k = 0; k < 128; k++) acc += s2[k] * W3[(size_t)k * 10 + t];
        out[(size_t)g * 10 + t] = fmaxf(acc, 0.f);
    }
}

// ---------------- launch ----------------
extern "C" void kernel_launch(void* const* d_in, const int* in_sizes, int n_in,
                              void* d_out, int out_size)
{
    const float* x  = (const float*)d_in[0];
    const int*   ei = (const int*)  d_in[1];
    int E = in_sizes[1] / 2;
    const int* src = ei;
    const int* dst = ei + E;

    const float* wl[4] = {(const float*)d_in[3], (const float*)d_in[6],
                          (const float*)d_in[9], (const float*)d_in[12]};
    const float* wr[4] = {(const float*)d_in[4], (const float*)d_in[7],
                          (const float*)d_in[10], (const float*)d_in[13]};
    const float* sb[4] = {(const float*)d_in[5], (const float*)d_in[8],
                          (const float*)d_in[11], (const float*)d_in[14]};
    const float* convw = (const float*)d_in[15];
    const float* convb = (const float*)d_in[16];
    const float* l1w   = (const float*)d_in[17];
    const float* l1b   = (const float*)d_in[18];
    const float* l2w   = (const float*)d_in[19];
    const float* l2b   = (const float*)d_in[20];
    const float* ow    = (const float*)d_in[21];
    const float* ob    = (const float*)d_in[22];

    float *pA, *pH, *pHL, *pHR, *pZ1;
    __nv_bfloat16 *pa0, *pa1, *pa2, *pb0, *pb1, *pb2, *pw0, *pw1, *pw2;
    __nv_bfloat16 *pt0, *pt1, *pc0, *pc1, *py0, *py1, *pl0, *pl1;
    cudaGetSymbolAddress((void**)&pA,  g_A);
    cudaGetSymbolAddress((void**)&pH,  g_H);
    cudaGetSymbolAddress((void**)&pHL, g_HL);
    cudaGetSymbolAddress((void**)&pHR, g_HR);
    cudaGetSymbolAddress((void**)&pZ1, g_z1);
    cudaGetSymbolAddress((void**)&pa0, g_a0);
    cudaGetSymbolAddress((void**)&pa1, g_a1);
    cudaGetSymbolAddress((void**)&pa2, g_a2);
    cudaGetSymbolAddress((void**)&pb0, g_b0);
    cudaGetSymbolAddress((void**)&pb1, g_b1);
    cudaGetSymbolAddress((void**)&pb2, g_b2);
    cudaGetSymbolAddress((void**)&pw0, g_w0);
    cudaGetSymbolAddress((void**)&pw1, g_w1);
    cudaGetSymbolAddress((void**)&pw2, g_w2);
    cudaGetSymbolAddress((void**)&pt0, g_t0);
    cudaGetSymbolAddress((void**)&pt1, g_t1);
    cudaGetSymbolAddress((void**)&pc0, g_c0);
    cudaGetSymbolAddress((void**)&pc1, g_c1);
    cudaGetSymbolAddress((void**)&py0, g_y0);
    cudaGetSymbolAddress((void**)&py1, g_y1);
    cudaGetSymbolAddress((void**)&pl0, g_l0);
    cudaGetSymbolAddress((void**)&pl1, g_l1);

    cudaFuncSetAttribute(gemm_sage_tc, cudaFuncAttributeMaxDynamicSharedMemorySize, GSMZ);
    cudaFuncSetAttribute(conv_tc, cudaFuncAttributeMaxDynamicSharedMemorySize, CSMZ);
    cudaFuncSetAttribute(lin1_tc, cudaFuncAttributeMaxDynamicSharedMemorySize, CSMZ);

    // preprocessing
    zero_f<<<(NB*PP*PP + 255)/256, 256>>>(pA, NB*PP*PP);
    build_adj<<<(E + 255)/256, 256>>>(src, dst, E, pA);
    norm_adj<<<NN/8, 256>>>(pA);
    nan_split3<<<(NN*FF + 255)/256, 256>>>(x, pa0, pa1, pa2, NN*FF);
    zero_f<<<(NB*HH + 255)/256, 256>>>(pZ1, NB*HH);
    prep_split<<<(PREP_TOTAL + 255)/256, 256>>>(
        wl[0], wr[0], wl[1], wr[1], wl[2], wr[2], wl[3], wr[3],
        convw, l1w, pw0, pw1, pw2, pc0, pc1, pl0, pl1);

    // 4 SAGE layers — bf16 3-plane 6-product TC GEMMs (R7 chains) + exact combine
    __nv_bfloat16 *i0 = pa0, *i1 = pa1, *i2 = pa2;
    __nv_bfloat16 *o0 = pb0, *o1 = pb1, *o2 = pb2;
    for (int l = 0; l < 4; l++) {
        int K = (l == 0) ? FF : HH;
        size_t f0 = (size_t)(2*l)   * HH * HH;
        size_t f1 = (size_t)(2*l+1) * HH * HH;
        gemm_sage_tc<<<dim3(8, NN/128), 256, GSMZ>>>(
            i0, i1, i2,
            pw0+f0, pw1+f0, pw2+f0,
            pw0+f1, pw1+f1, pw2+f1,
            pHL, pHR, K);
        int last = (l == 3);
        sage_combine<<<NB, 256>>>(pHL, pHR, sb[l], pH, o0, o1, o2, pA,
                                  last, !last);
        __nv_bfloat16* tmp;
        tmp = i0; i0 = o0; o0 = tmp;
        tmp = i1; i1 = o1; o1 = tmp;
        tmp = i2; i2 = o2; o2 = tmp;
    }

    // SortPool (exact fp32 keys) -> conv1d TC -> lin1 TC -> MLP
    sort_topk2<<<NB, 256>>>(pH, pt0, pt1);
    conv_tc<<<dim3(2, MCONV/128), 256, CSMZ>>>(pt0, pt1, pc0, pc1, py0, py1, convb);
    lin1_tc<<<dim3(2, 4, LOUT), 256, CSMZ>>>(py0, py1, pl0, pl1, pZ1);
    mlp_kernel<<<NB, 256>>>(pZ1, l1b, l2w, l2b, ow, ob, (float*)d_out);
}

// round 16
// speedup vs baseline: 1.3507x; 1.3507x over previous
#include <cuda_runtime.h>
#include <cuda_bf16.h>
#include <cuda_fp16.h>
#include <math.h>
#include <stdint.h>

// ---------------- problem constants ----------------
#define NB       512
#define PP       64
#define NN       (NB*PP)      // 32768
#define FF       128
#define HH       256
#define KSORT    30
#define LOUT     27
#define MCONV    (NB*LOUT)    // 13824

// ---------------- static scratch ----------------
__device__ __align__(16) float g_A  [NB*PP*PP];
__device__ __align__(16) float g_H  [NN*HH];      // fp32 activations (sort keys)
__device__ __align__(16) float g_HL [NN*HH];
__device__ __align__(16) float g_HR [NN*HH];
__device__ __align__(16) float g_z1 [NB*HH];
// fp16 2-plane activations ping/pong
__device__ __align__(16) __half g_a0[NN*HH], g_a1[NN*HH];
__device__ __align__(16) __half g_b0[NN*HH], g_b1[NN*HH];
// fp16 sage weight planes [8 mats][256][K]
__device__ __align__(16) __half g_w0[8*HH*HH], g_w1[8*HH*HH];
// conv path (bf16 2-plane)
__device__ __align__(16) __nv_bfloat16 g_t0[NB*KSORT*HH], g_t1[NB*KSORT*HH];
__device__ __align__(16) __nv_bfloat16 g_c0[HH*1024],     g_c1[HH*1024];
// conv split-K partials (fp32) and output bf16 split-2 planes
__device__ __align__(16) float g_yp0[MCONV*HH], g_yp1[MCONV*HH];
__device__ __align__(16) __nv_bfloat16 g_y0[MCONV*HH], g_y1[MCONV*HH];
// lin1 weight planes [ts][n][o]
__device__ __align__(16) __nv_bfloat16 g_l0[LOUT*HH*HH], g_l1[LOUT*HH*HH];

// ---------------- helpers ----------------
__device__ __forceinline__ uint32_t smem_u32(const void* p) {
    uint32_t a;
    asm("{ .reg .u64 t; cvta.to.shared.u64 t, %1; cvt.u32.u64 %0, t; }" : "=r"(a) : "l"(p));
    return a;
}
__device__ __forceinline__ void cpasync16(uint32_t dst, const void* src) {
    asm volatile("cp.async.cg.shared.global [%0], [%1], 16;" :: "r"(dst), "l"(src));
}
__device__ __forceinline__ void ldsm4(uint32_t* r, uint32_t addr) {
    asm volatile("ldmatrix.sync.aligned.m8n8.x4.shared.b16 {%0,%1,%2,%3}, [%4];"
        : "=r"(r[0]), "=r"(r[1]), "=r"(r[2]), "=r"(r[3]) : "r"(addr));
}
__device__ __forceinline__ void mma16bf(float* d, uint32_t a0, uint32_t a1,
                                        uint32_t a2, uint32_t a3,
                                        uint32_t b0, uint32_t b1) {
    asm volatile(
        "mma.sync.aligned.m16n8k16.row.col.f32.bf16.bf16.f32 "
        "{%0,%1,%2,%3}, {%4,%5,%6,%7}, {%8,%9}, {%0,%1,%2,%3};"
        : "+f"(d[0]), "+f"(d[1]), "+f"(d[2]), "+f"(d[3])
        : "r"(a0), "r"(a1), "r"(a2), "r"(a3), "r"(b0), "r"(b1));
}
__device__ __forceinline__ void mma16h(float* d, const uint32_t* a,
                                       uint32_t b0, uint32_t b1) {
    asm volatile(
        "mma.sync.aligned.m16n8k16.row.col.f32.f16.f16.f32 "
        "{%0,%1,%2,%3}, {%4,%5,%6,%7}, {%8,%9}, {%0,%1,%2,%3};"
        : "+f"(d[0]), "+f"(d[1]), "+f"(d[2]), "+f"(d[3])
        : "r"(a[0]), "r"(a[1]), "r"(a[2]), "r"(a[3]), "r"(b0), "r"(b1));
}
struct H2S { __half x, y; };
__device__ __forceinline__ H2S h2_split(float v) {
    H2S r;
    r.x = __float2half_rn(v);
    float rem = v - __half2float(r.x);
    r.y = __float2half_rn(rem);
    return r;
}
__device__ __forceinline__ __nv_bfloat162 bf2_split(float v) {
    __nv_bfloat16 h0 = __float2bfloat16(v);
    __nv_bfloat16 h1 = __float2bfloat16(v - __bfloat162float(h0));
    __nv_bfloat162 r; r.x = h0; r.y = h1; return r;
}

// ===== SAGE GEMM (verbatim R14/R12/R11 schedule: key path, bit-identical) ===
#define GPROW_B   80
#define GA_PLANE  (128*GPROW_B)
#define GB_PLANE  (64*GPROW_B)
#define GSTAGE    (2*GA_PLANE + 2*GB_PLANE)
#define GSMZ      (3*GSTAGE)

__global__ __launch_bounds__(256, 2) void gemm_sage_tc(
    const __half* __restrict__ A0, const __half* __restrict__ A1,
    const __half* __restrict__ L0, const __half* __restrict__ L1,
    const __half* __restrict__ R0, const __half* __restrict__ R1,
    float* __restrict__ Cl, float* __restrict__ Cr, int K)
{
    extern __shared__ char smem[];
    const int t    = threadIdx.x;
    const int lane = t & 31;
    const int wid  = t >> 5;
    const int wm   = wid & 3;
    const int wn   = wid >> 2;
    const int m0   = blockIdx.y * 128;
    const int sel  = blockIdx.x >> 2;
    const int n0   = (blockIdx.x & 3) * 64;
    const int lr   = lane >> 2;
    const int lc   = lane & 3;
    const int nch  = K >> 5;

    const __half* W0 = sel ? R0 : L0;
    const __half* W1 = sel ? R1 : L1;
    float* C = sel ? Cr : Cl;

    uint32_t sbase = smem_u32(smem);

    const int l15    = lane & 15;
    const int koff_a = (lane >> 4) * 16;
    const int brow_l = ((lane >> 4) << 3) + (lane & 7);
    const int koff_b = ((lane >> 3) & 1) * 16;

    auto ld_stage = [&](int stage, int c) {
        uint32_t sb = sbase + stage * GSTAGE;
        int kt = c << 5;
        #pragma unroll
        for (int i = 0; i < 6; i++) {
            int idx = t + i * 256;
            if (idx < 1024) {
                int pl = idx >> 9, rem = idx & 511;
                int row = rem >> 2, q = rem & 3;
                const __half* P = pl ? A1 : A0;
                cpasync16(sb + pl * GA_PLANE + row * GPROW_B + q * 16,
                          P + (size_t)(m0 + row) * K + kt + q * 8);
            } else {
                int idx2 = idx - 1024;
                int pl = idx2 >> 8, rem = idx2 & 255;
                int row = rem >> 2, q = rem & 3;
                const __half* P = pl ? W1 : W0;
                cpasync16(sb + 2 * GA_PLANE + pl * GB_PLANE + row * GPROW_B + q * 16,
                          P + (size_t)(n0 + row) * K + kt + q * 8);
            }
        }
        asm volatile("cp.async.commit_group;" ::: "memory");
    };

    float acc_hi[2][4][4], acc_lo[2][4][4];
    #pragma unroll
    for (int m = 0; m < 2; m++)
        #pragma unroll
        for (int j = 0; j < 4; j++)
            #pragma unroll
            for (int q = 0; q < 4; q++) { acc_hi[m][j][q] = 0.f; acc_lo[m][j][q] = 0.f; }

    ld_stage(0, 0);
    if (nch > 1) ld_stage(1, 1);

    int st = 0;
    for (int c = 0; c < nch; c++) {
        if (c + 1 < nch) asm volatile("cp.async.wait_group 1;" ::: "memory");
        else             asm volatile("cp.async.wait_group 0;" ::: "memory");
        __syncthreads();
        if (c + 2 < nch) {
            int st2 = st + 2; if (st2 >= 3) st2 -= 3;
            ld_stage(st2, c + 2);
        }

        uint32_t sb = sbase + st * GSTAGE;

        #pragma unroll
        for (int s = 0; s < 2; s++) {
            uint32_t a0f[2][4], a1f[2][4];
            #pragma unroll
            for (int m = 0; m < 2; m++) {
                uint32_t rowb = (uint32_t)((wm * 32 + m * 16 + l15) * GPROW_B
                                           + s * 32 + koff_a);
                ldsm4(a0f[m], sb + rowb);
                ldsm4(a1f[m], sb + GA_PLANE + rowb);
            }
            #pragma unroll
            for (int jp = 0; jp < 2; jp++) {
                uint32_t nrow = sb + 2 * GA_PLANE
                    + (uint32_t)((wn * 32 + jp * 16 + brow_l) * GPROW_B
                                 + s * 32 + koff_b);
                uint32_t b0[4], b1[4];
                ldsm4(b0, nrow);
                ldsm4(b1, nrow + GB_PLANE);
                // pass 1: all hi (a0*b0)
                #pragma unroll
                for (int jj = 0; jj < 2; jj++)
                    #pragma unroll
                    for (int m = 0; m < 2; m++)
                        mma16h(acc_hi[m][jp*2+jj], a0f[m], b0[2*jj], b0[2*jj+1]);
                // pass 2: all lo (a0*b1)
                #pragma unroll
                for (int jj = 0; jj < 2; jj++)
                    #pragma unroll
                    for (int m = 0; m < 2; m++)
                        mma16h(acc_lo[m][jp*2+jj], a0f[m], b1[2*jj], b1[2*jj+1]);
                // pass 3: all lo (a1*b0)
                #pragma unroll
                for (int jj = 0; jj < 2; jj++)
                    #pragma unroll
                    for (int m = 0; m < 2; m++)
                        mma16h(acc_lo[m][jp*2+jj], a1f[m], b0[2*jj], b0[2*jj+1]);
            }
        }
        if (++st == 3) st = 0;
    }

    #pragma unroll
    for (int m = 0; m < 2; m++) {
        int row = m0 + wm * 32 + m * 16 + lr;
        #pragma unroll
        for (int j = 0; j < 4; j++) {
            int col = n0 + wn * 32 + j * 8 + 2 * lc;
            float2 v0 = make_float2(acc_hi[m][j][0] + acc_lo[m][j][0],
                                    acc_hi[m][j][1] + acc_lo[m][j][1]);
            float2 v1 = make_float2(acc_hi[m][j][2] + acc_lo[m][j][2],
                                    acc_hi[m][j][3] + acc_lo[m][j][3]);
            *(float2*)(C + (size_t)row * 256 + col)       = v0;
            *(float2*)(C + (size_t)(row + 8) * 256 + col) = v1;
        }
    }
}

// ---------------- prep kernels ----------------
__global__ void zero_f(float* p, int n) {
    int i = blockIdx.x * 256 + threadIdx.x;
    if (i < n) p[i] = 0.f;
}

__global__ void nan_split2h(const float* __restrict__ x,
                            __half* __restrict__ p0, __half* __restrict__ p1, int n) {
    int i = blockIdx.x * 256 + threadIdx.x;
    if (i >= n) return;
    float v = x[i]; v = isnan(v) ? 0.f : v;
    H2S s = h2_split(v);
    p0[i] = s.x; p1[i] = s.y;
}

__global__ void build_adj(const int* __restrict__ src, const int* __restrict__ dst,
                          int E, float* __restrict__ A) {
    int e = blockIdx.x * 256 + threadIdx.x;
    if (e >= E) return;
    int s = src[e], d = dst[e];
    int g = d >> 6;
    atomicAdd(&A[((size_t)g << 12) + ((size_t)(d & 63) << 6) + (s & 63)], 1.0f);
}

__global__ void norm_adj(float* __restrict__ A) {
    int row  = blockIdx.x * 8 + (threadIdx.x >> 5);
    int lane = threadIdx.x & 31;
    float* rp = A + (size_t)row * 64;
    float v0 = rp[lane], v1 = rp[lane + 32];
    float s = v0 + v1;
    #pragma unroll
    for (int o = 16; o > 0; o >>= 1) s += __shfl_xor_sync(0xffffffffu, s, o);
    float inv = 1.f / fmaxf(s, 1.f);
    rp[lane] = v0 * inv; rp[lane + 32] = v1 * inv;
}

// ===== merged weight-split prep (verbatim R14) ===============================
#define W1_ELEMS   (LOUT*256*256)            // 1769472
#define CV_ELEMS   (256*1024)                // 262144
#define SG_ELEMS   (2*(128+256+256+256)*256) // 458752
#define PREP_TOTAL (W1_ELEMS + CV_ELEMS + SG_ELEMS)

__global__ void prep_split(
    const float* __restrict__ wl0, const float* __restrict__ wr0,
    const float* __restrict__ wl1, const float* __restrict__ wr1,
    const float* __restrict__ wl2, const float* __restrict__ wr2,
    const float* __restrict__ wl3, const float* __restrict__ wr3,
    const float* __restrict__ convw, const float* __restrict__ l1w,
    __half* __restrict__ pw0, __half* __restrict__ pw1,
    __nv_bfloat16* __restrict__ pc0, __nv_bfloat16* __restrict__ pc1,
    __nv_bfloat16* __restrict__ pl0, __nv_bfloat16* __restrict__ pl1)
{
    int idx = blockIdx.x * 256 + threadIdx.x;
    if (idx >= PREP_TOTAL) return;
    if (idx < W1_ELEMS) {
        int ts = idx >> 16;
        int rem = idx & 65535;
        int n = rem >> 8, o = rem & 255;
        float v = l1w[((size_t)(o * LOUT + ts)) * 256 + n];
        __nv_bfloat16 h0 = __float2bfloat16(v);
        pl0[idx] = h0;
        pl1[idx] = __float2bfloat16(v - __bfloat162float(h0));
    } else if (idx < W1_ELEMS + CV_ELEMS) {
        int i2 = idx - W1_ELEMS;
        int o = i2 >> 10, k = i2 & 1023;
        int s = k >> 8, i = k & 255;
        float v = convw[((size_t)(o * 256 + i)) * 4 + s];
        __nv_bfloat16 h0 = __float2bfloat16(v);
        pc0[i2] = h0;
        pc1[i2] = __float2bfloat16(v - __bfloat162float(h0));
    } else {
        int i2 = idx - (W1_ELEMS + CV_ELEMS);
        int mat, off, K;
        if (i2 < 65536) { mat = i2 >> 15; off = i2 & 32767; K = 128; }
        else {
            int j = i2 - 65536;
            mat = 2 + (j >> 16); off = j & 65535; K = 256;
        }
        const float* src;
        switch (mat) {
            case 0: src = wl0; break;
            case 1: src = wr0; break;
            case 2: src = wl1; break;
            case 3: src = wr1; break;
            case 4: src = wl2; break;
            case 5: src = wr2; break;
            case 6: src = wl3; break;
            default: src = wr3; break;
        }
        int k = off >> 8, n = off & 255;
        H2S s = h2_split(src[off]);
        size_t d = (size_t)mat * (HH * HH) + (size_t)n * K + k;
        pw0[d] = s.x; pw1[d] = s.y;
    }
}

// ------------- SAGE combine (verbatim R14: R1-exact chains) -----------------
__global__ __launch_bounds__(256) void sage_combine(
    const float* __restrict__ HL, const float* __restrict__ HR,
    const float* __restrict__ bias, float* __restrict__ Hout,
    __half* __restrict__ p0, __half* __restrict__ p1,
    const float* __restrict__ Aadj, int emit_h, int emit_planes)
{
    __shared__ float As[64][64];
    __shared__ float HLs[64][128];
    int g = blockIdx.x, t = threadIdx.x;
    const float* Ag = Aadj + ((size_t)g << 12);

    #pragma unroll
    for (int h = 0; h < 4; h++) {
        int idx = t + h * 256;
        int n = idx >> 4, k4 = (idx & 15) * 4;
        float4 v = *reinterpret_cast<const float4*>(Ag + (size_t)n * 64 + k4);
        As[k4 + 0][n] = v.x; As[k4 + 1][n] = v.y;
        As[k4 + 2][n] = v.z; As[k4 + 3][n] = v.w;
    }

    int ngrp = t >> 4;
    int cgrp = t & 15;

    for (int ch = 0; ch < 2; ch++) {
        __syncthreads();
        #pragma unroll
        for (int h = 0; h < 8; h++) {
            int idx = t + h * 256;
            int k = idx >> 5, c4 = (idx & 31) * 4;
            *reinterpret_cast<float4*>(&HLs[k][c4]) =
                *reinterpret_cast<const float4*>(HL + ((size_t)(g * 64 + k)) * HH + ch * 128 + c4);
        }
        __syncthreads();

        float acc[4][8];
        #pragma unroll
        for (int i = 0; i < 4; i++)
            #pragma unroll
            for (int j = 0; j < 8; j++) acc[i][j] = 0.f;

        #pragma unroll 4
        for (int k = 0; k < 64; k++) {
            float a[4], b[8];
            *reinterpret_cast<float4*>(&a[0]) = *reinterpret_cast<const float4*>(&As[k][ngrp * 4]);
            *reinterpret_cast<float4*>(&b[0]) = *reinterpret_cast<const float4*>(&HLs[k][cgrp * 8]);
            *reinterpret_cast<float4*>(&b[4]) = *reinterpret_cast<const float4*>(&HLs[k][cgrp * 8 + 4]);
            #pragma unroll
            for (int i = 0; i < 4; i++)
                #pragma unroll
                for (int j = 0; j < 8; j++) acc[i][j] += a[i] * b[j];
        }
        #pragma unroll
        for (int i = 0; i < 4; i++) {
            int n = ngrp * 4 + i;
            size_t base = ((size_t)(g * 64 + n)) * HH + ch * 128 + cgrp * 8;
            #pragma unroll
            for (int j = 0; j < 8; j++) {
                float v = acc[i][j] + bias[ch * 128 + cgrp * 8 + j] + HR[base + j];
                float h = fmaxf(v, 0.f);
                if (emit_h) Hout[base + j] = h;
                if (emit_planes) {
                    H2S s = h2_split(h);
                    p0[base + j] = s.x; p1[base + j] = s.y;
                }
            }
        }
    }
}

// ------------- SortPool (verbatim) -------------------------------------------
__global__ __launch_bounds__(256) void sort_topk2(
    const float* __restrict__ H,
    __nv_bfloat16* __restrict__ t0, __nv_bfloat16* __restrict__ t1)
{
    int g = blockIdx.x, t = threadIdx.x;
    __shared__ float keys[64];
    __shared__ int   sel[KSORT];
    if (t < 64) keys[t] = H[((size_t)(g * 64 + t)) * HH + 255];
    __syncthreads();
    if (t < 64) {
        float kv = keys[t];
        int r = 0;
        #pragma unroll
        for (int m = 0; m < 64; m++) {
            float km = keys[m];
            r += (km > kv) || (km == kv && m < t);
        }
        if (r < KSORT) sel[r] = t;
    }
    __syncthreads();
    for (int idx = t; idx < KSORT * HH; idx += 256) {
        int r = idx >> 8, c = idx & 255;
        float v = H[((size_t)(g * 64 + sel[r])) * HH + c];
        __nv_bfloat16 h0 = __float2bfloat16(v);
        size_t d = (size_t)g * KSORT * HH + idx;
        t0[d] = h0;
        t1[d] = __float2bfloat16(v - __bfloat162float(h0));
    }
}

// ============ conv1d TC GEMM, split-K=2: fp32 partials (no bias/relu) ========
#define CPROW_B   80
#define CPLANE_B  (128*CPROW_B)
#define CSTAGE_B  (4*CPLANE_B)
#define CSMZ      (2*CSTAGE_B)

__global__ __launch_bounds__(256) void conv_tc_part(
    const __nv_bfloat16* __restrict__ T0, const __nv_bfloat16* __restrict__ T1,
    const __nv_bfloat16* __restrict__ W0, const __nv_bfloat16* __restrict__ W1,
    float* __restrict__ Yp0, float* __restrict__ Yp1)
{
    extern __shared__ char smem[];
    const int t    = threadIdx.x;
    const int lane = t & 31;
    const int wid  = t >> 5;
    const int wm   = wid & 3;
    const int wn   = wid >> 2;
    const int m0   = blockIdx.y * 128;
    const int n0   = blockIdx.x * 128;
    const int kb   = blockIdx.z * 16;       // K-chunk base (split-K=2)
    const int lr   = lane >> 2;
    const int lc   = lane & 3;
    const int nch  = 16;

    float* Yp = blockIdx.z ? Yp1 : Yp0;

    uint32_t sbase = smem_u32(smem);

    auto ld_stage = [&](int stage, int c) {
        uint32_t sb = sbase + stage * CSTAGE_B;
        int kt = (kb + c) << 5;
        int sp = kt >> 8, ko = kt & 255;
        #pragma unroll
        for (int i = 0; i < 8; i++) {
            int idx = t + i * 256;
            int pl  = idx >> 9;
            int rem = idx & 511;
            int row = rem >> 2, q = rem & 3;
            uint32_t dst = sb + pl * CPLANE_B + row * CPROW_B + q * 16;
            const __nv_bfloat16* src;
            if (pl < 2) {
                const __nv_bfloat16* P = (pl == 0) ? T0 : T1;
                int m = m0 + row;
                int g = m / 27, tp = m - g * 27;
                src = P + (size_t)((g * 30 + tp + sp) * 256 + ko) + q * 8;
            } else {
                const __nv_bfloat16* P = (pl == 2) ? W0 : W1;
                src = P + (size_t)(n0 + row) * 1024 + kt + q * 8;
            }
            cpasync16(dst, src);
        }
        asm volatile("cp.async.commit_group;" ::: "memory");
    };

    float acc[2][8][4];
    #pragma unroll
    for (int m = 0; m < 2; m++)
        #pragma unroll
        for (int j = 0; j < 8; j++)
            #pragma unroll
            for (int q = 0; q < 4; q++) acc[m][j][q] = 0.f;

    ld_stage(0, 0);
    ld_stage(1, 1);

    for (int c = 0; c < nch; c++) {
        if (c + 1 < nch) asm volatile("cp.async.wait_group 1;" ::: "memory");
        else             asm volatile("cp.async.wait_group 0;" ::: "memory");
        __syncthreads();

        const char* sb = smem + (c & 1) * CSTAGE_B;

        #pragma unroll
        for (int s = 0; s < 2; s++) {
            int kc = s * 32 + lc * 4;
            uint32_t A0f[2][4], A1f[2][4];
            #pragma unroll
            for (int m = 0; m < 2; m++) {
                int r0 = (wm * 32 + m * 16 + lr) * CPROW_B;
                int r1 = r0 + 8 * CPROW_B;
                A0f[m][0] = *(const uint32_t*)(sb + r0 + kc);
                A0f[m][1] = *(const uint32_t*)(sb + r1 + kc);
                A0f[m][2] = *(const uint32_t*)(sb + r0 + kc + 16);
                A0f[m][3] = *(const uint32_t*)(sb + r1 + kc + 16);
                A1f[m][0] = *(const uint32_t*)(sb + CPLANE_B + r0 + kc);
                A1f[m][1] = *(const uint32_t*)(sb + CPLANE_B + r1 + kc);
                A1f[m][2] = *(const uint32_t*)(sb + CPLANE_B + r0 + kc + 16);
                A1f[m][3] = *(const uint32_t*)(sb + CPLANE_B + r1 + kc + 16);
            }
            #pragma unroll
            for (int j = 0; j < 8; j++) {
                int nr = (wn * 64 + j * 8 + lr) * CPROW_B;
                uint32_t b00 = *(const uint32_t*)(sb + 2*CPLANE_B + nr + kc);
                uint32_t b01 = *(const uint32_t*)(sb + 2*CPLANE_B + nr + kc + 16);
                uint32_t b10 = *(const uint32_t*)(sb + 3*CPLANE_B + nr + kc);
                uint32_t b11 = *(const uint32_t*)(sb + 3*CPLANE_B + nr + kc + 16);
                #pragma unroll
                for (int m = 0; m < 2; m++)
                    mma16bf(acc[m][j], A0f[m][0], A0f[m][1], A0f[m][2], A0f[m][3], b00, b01);
                #pragma unroll
                for (int m = 0; m < 2; m++)
                    mma16bf(acc[m][j], A0f[m][0], A0f[m][1], A0f[m][2], A0f[m][3], b10, b11);
                #pragma unroll
                for (int m = 0; m < 2; m++)
                    mma16bf(acc[m][j], A1f[m][0], A1f[m][1], A1f[m][2], A1f[m][3], b00, b01);
            }
        }
        if (c + 2 < nch) {
            __syncthreads();
            ld_stage(c & 1, c + 2);
        }
    }

    #pragma unroll
    for (int m = 0; m < 2; m++) {
        int row = m0 + wm * 32 + m * 16 + lr;
        #pragma unroll
        for (int j = 0; j < 8; j++) {
            int col = n0 + wn * 64 + j * 8 + 2 * lc;
            *(float2*)(Yp + (size_t)row * 256 + col) =
                make_float2(acc[m][j][0], acc[m][j][1]);
            *(float2*)(Yp + (size_t)(row + 8) * 256 + col) =
                make_float2(acc[m][j][2], acc[m][j][3]);
        }
    }
}

// conv finish: y = relu(p0 + p1 + bias) -> bf16 split-2 planes
__global__ void conv_fin(const float* __restrict__ P0, const float* __restrict__ P1,
                         const float* __restrict__ bias,
                         __nv_bfloat16* __restrict__ Y0, __nv_bfloat16* __restrict__ Y1)
{
    int i = blockIdx.x * 256 + threadIdx.x;
    if (i >= MCONV * HH) return;
    float v = fmaxf(P0[i] + P1[i] + bias[i & 255], 0.f);
    __nv_bfloat162 s = bf2_split(v);
    Y0[i] = s.x; Y1[i] = s.y;
}

// ============ lin1 TC GEMM (verbatim R14) ====================================
__global__ __launch_bounds__(256) void lin1_tc(
    const __nv_bfloat16* __restrict__ Y0, const __nv_bfloat16* __restrict__ Y1,
    const __nv_bfloat16* __restrict__ P0, const __nv_bfloat16* __restrict__ P1,
    float* __restrict__ Z)
{
    extern __shared__ char smem[];
    const int t    = threadIdx.x;
    const int lane = t & 31;
    const int wid  = t >> 5;
    const int wm   = wid & 3;
    const int wn   = wid >> 2;
    const int m0   = blockIdx.y * 128;
    const int n0   = blockIdx.x * 128;
    const int ts   = blockIdx.z;
    const int lr   = lane >> 2;
    const int lc   = lane & 3;
    const int nch  = 8;

    uint32_t sbase = smem_u32(smem);

    auto ld_stage = [&](int stage, int c) {
        uint32_t sb = sbase + stage * CSTAGE_B;
        int kt = c << 5;
        #pragma unroll
        for (int i = 0; i < 8; i++) {
            int idx = t + i * 256;
            int pl  = idx >> 9;
            int rem = idx & 511;
            int row = rem >> 2, q = rem & 3;
            uint32_t dst = sb + pl * CPLANE_B + row * CPROW_B + q * 16;
            const __nv_bfloat16* src;
            if (pl < 2) {
                const __nv_bfloat16* P = (pl == 0) ? Y0 : Y1;
                src = P + ((size_t)((m0 + row) * LOUT + ts)) * 256 + kt + q * 8;
            } else {
                const __nv_bfloat16* P = (pl == 2) ? P0 : P1;
                src = P + ((size_t)(ts * 256 + n0 + row)) * 256 + kt + q * 8;
            }
            cpasync16(dst, src);
        }
        asm volatile("cp.async.commit_group;" ::: "memory");
    };

    float acc[2][8][4];
    #pragma unroll
    for (int m = 0; m < 2; m++)
        #pragma unroll
        for (int j = 0; j < 8; j++)
            #pragma unroll
            for (int q = 0; q < 4; q++) acc[m][j][q] = 0.f;

    ld_stage(0, 0);
    ld_stage(1, 1);

    for (int c = 0; c < nch; c++) {
        if (c + 1 < nch) asm volatile("cp.async.wait_group 1;" ::: "memory");
        else             asm volatile("cp.async.wait_group 0;" ::: "memory");
        __syncthreads();

        const char* sb = smem + (c & 1) * CSTAGE_B;

        #pragma unroll
        for (int s = 0; s < 2; s++) {
            int kc = s * 32 + lc * 4;
            uint32_t A0f[2][4], A1f[2][4];
            #pragma unroll
            for (int m = 0; m < 2; m++) {
                int r0 = (wm * 32 + m * 16 + lr) * CPROW_B;
                int r1 = r0 + 8 * CPROW_B;
                A0f[m][0] = *(const uint32_t*)(sb + r0 + kc);
                A0f[m][1] = *(const uint32_t*)(sb + r1 + kc);
                A0f[m][2] = *(const uint32_t*)(sb + r0 + kc + 16);
                A0f[m][3] = *(const uint32_t*)(sb + r1 + kc + 16);
                A1f[m][0] = *(const uint32_t*)(sb + CPLANE_B + r0 + kc);
                A1f[m][1] = *(const uint32_t*)(sb + CPLANE_B + r1 + kc);
                A1f[m][2] = *(const uint32_t*)(sb + CPLANE_B + r0 + kc + 16);
                A1f[m][3] = *(const uint32_t*)(sb + CPLANE_B + r1 + kc + 16);
            }
            #pragma unroll
            for (int j = 0; j < 8; j++) {
                int nr = (wn * 64 + j * 8 + lr) * CPROW_B;
                uint32_t b00 = *(const uint32_t*)(sb + 2*CPLANE_B + nr + kc);
                uint32_t b01 = *(const uint32_t*)(sb + 2*CPLANE_B + nr + kc + 16);
                uint32_t b10 = *(const uint32_t*)(sb + 3*CPLANE_B + nr + kc);
                uint32_t b11 = *(const uint32_t*)(sb + 3*CPLANE_B + nr + kc + 16);
                #pragma unroll
                for (int m = 0; m < 2; m++)
                    mma16bf(acc[m][j], A0f[m][0], A0f[m][1], A0f[m][2], A0f[m][3], b00, b01);
                #pragma unroll
                for (int m = 0; m < 2; m++)
                    mma16bf(acc[m][j], A0f[m][0], A0f[m][1], A0f[m][2], A0f[m][3], b10, b11);
                #pragma unroll
                for (int m = 0; m < 2; m++)
                    mma16bf(acc[m][j], A1f[m][0], A1f[m][1], A1f[m][2], A1f[m][3], b00, b01);
            }
        }
        if (c + 2 < nch) {
            __syncthreads();
            ld_stage(c & 1, c + 2);
        }
    }

    #pragma unroll
    for (int m = 0; m < 2; m++) {
        int g = m0 + wm * 32 + m * 16 + lr;
        #pragma unroll
        for (int j = 0; j < 8; j++) {
            int col = n0 + wn * 64 + j * 8 + 2 * lc;
            atomicAdd(&Z[(size_t)g * 256 + col],           acc[m][j][0]);
            atomicAdd(&Z[(size_t)g * 256 + col + 1],       acc[m][j][1]);
            atomicAdd(&Z[(size_t)(g + 8) * 256 + col],     acc[m][j][2]);
            atomicAdd(&Z[(size_t)(g + 8) * 256 + col + 1], acc[m][j][3]);
        }
    }
}

// ------------- final MLP (verbatim) ------------------------------------------
__global__ __launch_bounds__(256) void mlp_kernel(
    const float* __restrict__ z1acc, const float* __restrict__ b1,
    const float* __restrict__ W2,   const float* __restrict__ b2,
    const float* __restrict__ W3,   const float* __restrict__ b3,
    float* __restrict__ out)
{
    int g = blockIdx.x, t = threadIdx.x;
    __shared__ float s1[256];
    __shared__ float s2[128];
    s1[t] = fmaxf(z1acc[(size_t)g * 256 + t] + b1[t], 0.f);
    __syncthreads();
    if (t < 128) {
        float acc = b2[t];
        #pragma unroll 8
        for (int k = 0; k < 256; k++) acc += s1[k] * W2[(size_t)k * 128 + t];
        s2[t] = fmaxf(acc, 0.f);
    }
    __syncthreads();
    if (t < 10) {
        float acc = b3[t];
        #pragma unroll
        for (int k = 0; k < 128; k++) acc += s2[k] * W3[(size_t)k * 10 + t];
        out[(size_t)g * 10 + t] = fmaxf(acc, 0.f);
    }
}

// ---------------- launch ----------------
extern "C" void kernel_launch(void* const* d_in, const int* in_sizes, int n_in,
                              void* d_out, int out_size)
{
    const float* x  = (const float*)d_in[0];
    const int*   ei = (const int*)  d_in[1];
    int E = in_sizes[1] / 2;
    const int* src = ei;
    const int* dst = ei + E;

    const float* wl[4] = {(const float*)d_in[3], (const float*)d_in[6],
                          (const float*)d_in[9], (const float*)d_in[12]};
    const float* wr[4] = {(const float*)d_in[4], (const float*)d_in[7],
                          (const float*)d_in[10], (const float*)d_in[13]};
    const float* sb[4] = {(const float*)d_in[5], (const float*)d_in[8],
                          (const float*)d_in[11], (const float*)d_in[14]};
    const float* convw = (const float*)d_in[15];
    const float* convb = (const float*)d_in[16];
    const float* l1w   = (const float*)d_in[17];
    const float* l1b   = (const float*)d_in[18];
    const float* l2w   = (const float*)d_in[19];
    const float* l2b   = (const float*)d_in[20];
    const float* ow    = (const float*)d_in[21];
    const float* ob    = (const float*)d_in[22];

    float *pA, *pH, *pHL, *pHR, *pZ1, *pYp0, *pYp1;
    __half *pa0, *pa1, *pb0, *pb1, *pw0, *pw1;
    __nv_bfloat16 *pt0, *pt1, *pc0, *pc1, *py0, *py1, *pl0, *pl1;
    cudaGetSymbolAddress((void**)&pA,   g_A);
    cudaGetSymbolAddress((void**)&pH,   g_H);
    cudaGetSymbolAddress((void**)&pHL,  g_HL);
    cudaGetSymbolAddress((void**)&pHR,  g_HR);
    cudaGetSymbolAddress((void**)&pZ1,  g_z1);
    cudaGetSymbolAddress((void**)&pYp0, g_yp0);
    cudaGetSymbolAddress((void**)&pYp1, g_yp1);
    cudaGetSymbolAddress((void**)&pa0, g_a0);
    cudaGetSymbolAddress((void**)&pa1, g_a1);
    cudaGetSymbolAddress((void**)&pb0, g_b0);
    cudaGetSymbolAddress((void**)&pb1, g_b1);
    cudaGetSymbolAddress((void**)&pw0, g_w0);
    cudaGetSymbolAddress((void**)&pw1, g_w1);
    cudaGetSymbolAddress((void**)&pt0, g_t0);
    cudaGetSymbolAddress((void**)&pt1, g_t1);
    cudaGetSymbolAddress((void**)&pc0, g_c0);
    cudaGetSymbolAddress((void**)&pc1, g_c1);
    cudaGetSymbolAddress((void**)&py0, g_y0);
    cudaGetSymbolAddress((void**)&py1, g_y1);
    cudaGetSymbolAddress((void**)&pl0, g_l0);
    cudaGetSymbolAddress((void**)&pl1, g_l1);

    cudaFuncSetAttribute(gemm_sage_tc, cudaFuncAttributeMaxDynamicSharedMemorySize, GSMZ);
    cudaFuncSetAttribute(conv_tc_part, cudaFuncAttributeMaxDynamicSharedMemorySize, CSMZ);
    cudaFuncSetAttribute(lin1_tc, cudaFuncAttributeMaxDynamicSharedMemorySize, CSMZ);

    // preprocessing
    zero_f<<<(NB*PP*PP + 255)/256, 256>>>(pA, NB*PP*PP);
    build_adj<<<(E + 255)/256, 256>>>(src, dst, E, pA);
    norm_adj<<<NN/8, 256>>>(pA);
    nan_split2h<<<(NN*FF + 255)/256, 256>>>(x, pa0, pa1, NN*FF);
    zero_f<<<(NB*HH + 255)/256, 256>>>(pZ1, NB*HH);
    prep_split<<<(PREP_TOTAL + 255)/256, 256>>>(
        wl[0], wr[0], wl[1], wr[1], wl[2], wr[2], wl[3], wr[3],
        convw, l1w, pw0, pw1, pc0, pc1, pl0, pl1);

    // 4 SAGE layers — fp16 2-plane 3-product TC GEMMs + exact combine
    __half *i0 = pa0, *i1 = pa1;
    __half *o0 = pb0, *o1 = pb1;
    for (int l = 0; l < 4; l++) {
        int K = (l == 0) ? FF : HH;
        size_t f0 = (size_t)(2*l)   * HH * HH;
        size_t f1 = (size_t)(2*l+1) * HH * HH;
        gemm_sage_tc<<<dim3(8, NN/128), 256, GSMZ>>>(
            i0, i1,
            pw0+f0, pw1+f0,
            pw0+f1, pw1+f1,
            pHL, pHR, K);
        int last = (l == 3);
        sage_combine<<<NB, 256>>>(pHL, pHR, sb[l], pH, o0, o1, pA,
                                  last, !last);
        __half* tmp;
        tmp = i0; i0 = o0; o0 = tmp;
        tmp = i1; i1 = o1; o1 = tmp;
    }

    // SortPool -> conv1d TC (split-K=2) -> finish -> lin1 TC -> MLP
    sort_topk2<<<NB, 256>>>(pH, pt0, pt1);
    conv_tc_part<<<dim3(2, MCONV/128, 2), 256, CSMZ>>>(pt0, pt1, pc0, pc1, pYp0, pYp1);
    conv_fin<<<(MCONV*HH + 255)/256, 256>>>(pYp0, pYp1, convb, py0, py1);
    lin1_tc<<<dim3(2, 4, LOUT), 256, CSMZ>>>(py0, py1, pl0, pl1, pZ1);
    mlp_kernel<<<NB, 256>>>(pZ1, l1b, l2w, l2b, ow, ob, (float*)d_out);
}

// round 17
// speedup vs baseline: 1.5329x; 1.1349x over previous
#include <cuda_runtime.h>
#include <cuda_bf16.h>
#include <cuda_fp16.h>
#include <math.h>
#include <stdint.h>

// ---------------- problem constants ----------------
#define NB       512
#define PP       64
#define NN       (NB*PP)      // 32768
#define FF       128
#define HH       256
#define KSORT    30
#define LOUT     27
#define MCONV    (NB*LOUT)    // 13824

// ---------------- static scratch ----------------
__device__ __align__(16) float g_A  [NB*PP*PP];
__device__ __align__(16) float g_H  [NN*HH];      // fp32 activations (sort keys)
__device__ __align__(16) float g_z1 [NB*HH];
// fp16 2-plane activations ping/pong
__device__ __align__(16) __half g_a0[NN*HH], g_a1[NN*HH];
__device__ __align__(16) __half g_b0[NN*HH], g_b1[NN*HH];
// fp16 sage weight planes [8 mats][256][K]
__device__ __align__(16) __half g_w0[8*HH*HH], g_w1[8*HH*HH];
// conv path (bf16 2-plane)
__device__ __align__(16) __nv_bfloat16 g_t0[NB*KSORT*HH], g_t1[NB*KSORT*HH];
__device__ __align__(16) __nv_bfloat16 g_c0[HH*1024],     g_c1[HH*1024];
// conv split-K partials (fp32) and output bf16 split-2 planes
__device__ __align__(16) float g_yp0[MCONV*HH], g_yp1[MCONV*HH];
__device__ __align__(16) __nv_bfloat16 g_y0[MCONV*HH], g_y1[MCONV*HH];
// lin1 weight planes [ts][n][o]
__device__ __align__(16) __nv_bfloat16 g_l0[LOUT*HH*HH], g_l1[LOUT*HH*HH];

// ---------------- helpers ----------------
__device__ __forceinline__ uint32_t smem_u32(const void* p) {
    uint32_t a;
    asm("{ .reg .u64 t; cvta.to.shared.u64 t, %1; cvt.u32.u64 %0, t; }" : "=r"(a) : "l"(p));
    return a;
}
__device__ __forceinline__ void cpasync16(uint32_t dst, const void* src) {
    asm volatile("cp.async.cg.shared.global [%0], [%1], 16;" :: "r"(dst), "l"(src));
}
__device__ __forceinline__ void ldsm4(uint32_t* r, uint32_t addr) {
    asm volatile("ldmatrix.sync.aligned.m8n8.x4.shared.b16 {%0,%1,%2,%3}, [%4];"
        : "=r"(r[0]), "=r"(r[1]), "=r"(r[2]), "=r"(r[3]) : "r"(addr));
}
__device__ __forceinline__ void mma16bf(float* d, uint32_t a0, uint32_t a1,
                                        uint32_t a2, uint32_t a3,
                                        uint32_t b0, uint32_t b1) {
    asm volatile(
        "mma.sync.aligned.m16n8k16.row.col.f32.bf16.bf16.f32 "
        "{%0,%1,%2,%3}, {%4,%5,%6,%7}, {%8,%9}, {%0,%1,%2,%3};"
        : "+f"(d[0]), "+f"(d[1]), "+f"(d[2]), "+f"(d[3])
        : "r"(a0), "r"(a1), "r"(a2), "r"(a3), "r"(b0), "r"(b1));
}
__device__ __forceinline__ void mma16h(float* d, const uint32_t* a,
                                       uint32_t b0, uint32_t b1) {
    asm volatile(
        "mma.sync.aligned.m16n8k16.row.col.f32.f16.f16.f32 "
        "{%0,%1,%2,%3}, {%4,%5,%6,%7}, {%8,%9}, {%0,%1,%2,%3};"
        : "+f"(d[0]), "+f"(d[1]), "+f"(d[2]), "+f"(d[3])
        : "r"(a[0]), "r"(a[1]), "r"(a[2]), "r"(a[3]), "r"(b0), "r"(b1));
}
struct H2S { __half x, y; };
__device__ __forceinline__ H2S h2_split(float v) {
    H2S r;
    r.x = __float2half_rn(v);
    float rem = v - __half2float(r.x);
    r.y = __float2half_rn(rem);
    return r;
}
__device__ __forceinline__ __nv_bfloat162 bf2_split(float v) {
    __nv_bfloat16 h0 = __float2bfloat16(v);
    __nv_bfloat16 h1 = __float2bfloat16(v - __bfloat162float(h0));
    __nv_bfloat162 r; r.x = h0; r.y = h1; return r;
}

// ===== fused SAGE layer: L/R GEMM (R14 numerics) + combine in epilogue ======
// grid (8, 256): n0 = bx*32, m-tile = by*128 (= graphs 2by, 2by+1 exactly).
// Per-accumulator MMA chains identical to R14 (hi<-a0b0; lo<-a0b1, a1b0;
// chunks/s ascending). HL/HR values = hi+lo (same fp32 add as R14 epilogue).
// Combine FFMA chain identical to R14's sage_combine (k ascending 0..63,
// v=(acc+bias)+HR, relu) -> bit-identical output H / planes.
#define GPROW_B   80
#define GA_PLANE  (128*GPROW_B)               // 10240
#define GB_PLANE  (32*GPROW_B)                // 2560
#define GSTAGE    (2*GA_PLANE + 4*GB_PLANE)   // 30720
#define GSMZ      (3*GSTAGE)                  // 92160

__global__ __launch_bounds__(256, 2) void sage_fused(
    const __half* __restrict__ A0, const __half* __restrict__ A1,
    const __half* __restrict__ L0, const __half* __restrict__ L1,
    const __half* __restrict__ R0, const __half* __restrict__ R1,
    const float* __restrict__ bias, float* __restrict__ Hout,
    __half* __restrict__ p0, __half* __restrict__ p1,
    const float* __restrict__ Aadj, int K, int emit_h, int emit_planes)
{
    extern __shared__ char smem[];
    const int t    = threadIdx.x;
    const int lane = t & 31;
    const int wid  = t >> 5;
    const int wm   = wid & 3;          // 4 warp-rows x 32 M
    const int wn   = wid >> 2;         // 2 warp-cols x 16 N
    const int m0   = blockIdx.y * 128;
    const int n0   = blockIdx.x * 32;
    const int lr   = lane >> 2;
    const int lc   = lane & 3;
    const int nch  = K >> 5;

    uint32_t sbase = smem_u32(smem);

    const int l15    = lane & 15;
    const int koff_a = (lane >> 4) * 16;
    const int brow_l = ((lane >> 4) << 3) + (lane & 7);
    const int koff_b = ((lane >> 3) & 1) * 16;

    auto ld_stage = [&](int stage, int c) {
        uint32_t sb = sbase + stage * GSTAGE;
        int kt = c << 5;
        #pragma unroll
        for (int i = 0; i < 6; i++) {
            int idx = t + i * 256;              // 0..1535
            if (idx < 1024) {                   // A: 2 planes x 128 rows x 4 quads
                int pl = idx >> 9, rem = idx & 511;
                int row = rem >> 2, q = rem & 3;
                const __half* P = pl ? A1 : A0;
                cpasync16(sb + pl * GA_PLANE + row * GPROW_B + q * 16,
                          P + (size_t)(m0 + row) * K + kt + q * 8);
            } else {                            // B: 4 planes (L0,L1,R0,R1) x 32 rows x 4 quads
                int idx2 = idx - 1024;          // 0..511
                int pl = idx2 >> 7, rem = idx2 & 127;
                int row = rem >> 2, q = rem & 3;
                const __half* P = (pl == 0) ? L0 : ((pl == 1) ? L1 : ((pl == 2) ? R0 : R1));
                cpasync16(sb + 2 * GA_PLANE + pl * GB_PLANE + row * GPROW_B + q * 16,
                          P + (size_t)(n0 + row) * K + kt + q * 8);
            }
        }
        asm volatile("cp.async.commit_group;" ::: "memory");
    };

    float hL[2][2][4], lL[2][2][4], hR[2][2][4], lR[2][2][4];
    #pragma unroll
    for (int m = 0; m < 2; m++)
        #pragma unroll
        for (int j = 0; j < 2; j++)
            #pragma unroll
            for (int q = 0; q < 4; q++) {
                hL[m][j][q] = 0.f; lL[m][j][q] = 0.f;
                hR[m][j][q] = 0.f; lR[m][j][q] = 0.f;
            }

    ld_stage(0, 0);
    if (nch > 1) ld_stage(1, 1);

    int st = 0;
    for (int c = 0; c < nch; c++) {
        if (c + 1 < nch) asm volatile("cp.async.wait_group 1;" ::: "memory");
        else             asm volatile("cp.async.wait_group 0;" ::: "memory");
        __syncthreads();
        if (c + 2 < nch) {
            int st2 = st + 2; if (st2 >= 3) st2 -= 3;
            ld_stage(st2, c + 2);
        }

        uint32_t sb = sbase + st * GSTAGE;

        #pragma unroll
        for (int s = 0; s < 2; s++) {
            uint32_t a0f[2][4], a1f[2][4];
            #pragma unroll
            for (int m = 0; m < 2; m++) {
                uint32_t rowb = (uint32_t)((wm * 32 + m * 16 + l15) * GPROW_B
                                           + s * 32 + koff_a);
                ldsm4(a0f[m], sb + rowb);
                ldsm4(a1f[m], sb + GA_PLANE + rowb);
            }
            uint32_t nrow = sb + 2 * GA_PLANE
                + (uint32_t)((wn * 16 + brow_l) * GPROW_B + s * 32 + koff_b);
            uint32_t bL0[4], bL1[4], bR0[4], bR1[4];
            ldsm4(bL0, nrow);
            ldsm4(bL1, nrow + GB_PLANE);
            ldsm4(bR0, nrow + 2 * GB_PLANE);
            ldsm4(bR1, nrow + 3 * GB_PLANE);
            // L passes (R14 per-acc order: hi a0b0; lo a0b1; lo a1b0)
            #pragma unroll
            for (int jj = 0; jj < 2; jj++)
                #pragma unroll
                for (int m = 0; m < 2; m++)
                    mma16h(hL[m][jj], a0f[m], bL0[2*jj], bL0[2*jj+1]);
            #pragma unroll
            for (int jj = 0; jj < 2; jj++)
                #pragma unroll
                for (int m = 0; m < 2; m++)
                    mma16h(lL[m][jj], a0f[m], bL1[2*jj], bL1[2*jj+1]);
            #pragma unroll
            for (int jj = 0; jj < 2; jj++)
                #pragma unroll
                for (int m = 0; m < 2; m++)
                    mma16h(lL[m][jj], a1f[m], bL0[2*jj], bL0[2*jj+1]);
            // R passes
            #pragma unroll
            for (int jj = 0; jj < 2; jj++)
                #pragma unroll
                for (int m = 0; m < 2; m++)
                    mma16h(hR[m][jj], a0f[m], bR0[2*jj], bR0[2*jj+1]);
            #pragma unroll
            for (int jj = 0; jj < 2; jj++)
                #pragma unroll
                for (int m = 0; m < 2; m++)
                    mma16h(lR[m][jj], a0f[m], bR1[2*jj], bR1[2*jj+1]);
            #pragma unroll
            for (int jj = 0; jj < 2; jj++)
                #pragma unroll
                for (int m = 0; m < 2; m++)
                    mma16h(lR[m][jj], a1f[m], bR0[2*jj], bR0[2*jj+1]);
        }
        if (++st == 3) st = 0;
    }

    // ---------------- fused combine epilogue ----------------
    __syncthreads();   // all warps done with stage smem
    float* HLs = (float*)smem;                  // [128][33] 16896 B
    float* HRs = (float*)(smem + 16896);        // [128][33]
    float* As2 = (float*)(smem + 33792);        // [2][64][65] 33280 B

    #pragma unroll
    for (int m = 0; m < 2; m++) {
        #pragma unroll
        for (int jj = 0; jj < 2; jj++) {
            int row = wm * 32 + m * 16 + lr;
            int col = wn * 16 + jj * 8 + 2 * lc;
            HLs[row * 33 + col]           = hL[m][jj][0] + lL[m][jj][0];
            HLs[row * 33 + col + 1]       = hL[m][jj][1] + lL[m][jj][1];
            HLs[(row + 8) * 33 + col]     = hL[m][jj][2] + lL[m][jj][2];
            HLs[(row + 8) * 33 + col + 1] = hL[m][jj][3] + lL[m][jj][3];
            HRs[row * 33 + col]           = hR[m][jj][0] + lR[m][jj][0];
            HRs[row * 33 + col + 1]       = hR[m][jj][1] + lR[m][jj][1];
            HRs[(row + 8) * 33 + col]     = hR[m][jj][2] + lR[m][jj][2];
            HRs[(row + 8) * 33 + col + 1] = hR[m][jj][3] + lR[m][jj][3];
        }
    }
    // load A for the 2 graphs of this m-tile, transposed: As2[gg][k][n]
    {
        const float* Ag = Aadj + ((size_t)blockIdx.y << 13);  // 2*4096 floats
        for (int i = t; i < 8192; i += 256) {
            int gg = i >> 12, rem = i & 4095;
            int n = rem >> 6, k = rem & 63;      // A[g][n][k]
            As2[gg * 4160 + k * 65 + n] = Ag[i];
        }
    }
    __syncthreads();

    {
        const int gg   = t >> 7;          // 0..1 (graph within tile)
        const int tt   = t & 127;
        const int ngrp = tt >> 3;         // 0..15 -> 4 nodes
        const int cgrp = tt & 7;          // 0..7  -> 4 cols
        float acc[4][4];
        #pragma unroll
        for (int i = 0; i < 4; i++)
            #pragma unroll
            for (int j = 0; j < 4; j++) acc[i][j] = 0.f;

        const float* Ab = As2 + gg * 4160 + ngrp * 4;
        const float* Hb = HLs + (gg * 64) * 33 + cgrp * 4;
        #pragma unroll 4
        for (int k = 0; k < 64; k++) {
            float a0 = Ab[k * 65 + 0], a1 = Ab[k * 65 + 1];
            float a2 = Ab[k * 65 + 2], a3 = Ab[k * 65 + 3];
            float b0 = Hb[k * 33 + 0], b1 = Hb[k * 33 + 1];
            float b2 = Hb[k * 33 + 2], b3 = Hb[k * 33 + 3];
            acc[0][0] += a0 * b0; acc[0][1] += a0 * b1; acc[0][2] += a0 * b2; acc[0][3] += a0 * b3;
            acc[1][0] += a1 * b0; acc[1][1] += a1 * b1; acc[1][2] += a1 * b2; acc[1][3] += a1 * b3;
            acc[2][0] += a2 * b0; acc[2][1] += a2 * b1; acc[2][2] += a2 * b2; acc[2][3] += a2 * b3;
            acc[3][0] += a3 * b0; acc[3][1] += a3 * b1; acc[3][2] += a3 * b2; acc[3][3] += a3 * b3;
        }
        #pragma unroll
        for (int i = 0; i < 4; i++) {
            int node = ngrp * 4 + i;
            #pragma unroll
            for (int j = 0; j < 4; j++) {
                int cc = cgrp * 4 + j;
                float v = acc[i][j] + bias[n0 + cc] + HRs[(gg * 64 + node) * 33 + cc];
                float h = fmaxf(v, 0.f);
                size_t base = ((size_t)(m0 + gg * 64 + node)) * 256 + n0 + cc;
                if (emit_h) Hout[base] = h;
                if (emit_planes) {
                    H2S s = h2_split(h);
                    p0[base] = s.x; p1[base] = s.y;
                }
            }
        }
    }
}

// ---------------- prep kernels ----------------
__global__ void zero_f(float* p, int n) {
    int i = blockIdx.x * 256 + threadIdx.x;
    if (i < n) p[i] = 0.f;
}

__global__ void nan_split2h(const float* __restrict__ x,
                            __half* __restrict__ p0, __half* __restrict__ p1, int n) {
    int i = blockIdx.x * 256 + threadIdx.x;
    if (i >= n) return;
    float v = x[i]; v = isnan(v) ? 0.f : v;
    H2S s = h2_split(v);
    p0[i] = s.x; p1[i] = s.y;
}

__global__ void build_adj(const int* __restrict__ src, const int* __restrict__ dst,
                          int E, float* __restrict__ A) {
    int e = blockIdx.x * 256 + threadIdx.x;
    if (e >= E) return;
    int s = src[e], d = dst[e];
    int g = d >> 6;
    atomicAdd(&A[((size_t)g << 12) + ((size_t)(d & 63) << 6) + (s & 63)], 1.0f);
}

__global__ void norm_adj(float* __restrict__ A) {
    int row  = blockIdx.x * 8 + (threadIdx.x >> 5);
    int lane = threadIdx.x & 31;
    float* rp = A + (size_t)row * 64;
    float v0 = rp[lane], v1 = rp[lane + 32];
    float s = v0 + v1;
    #pragma unroll
    for (int o = 16; o > 0; o >>= 1) s += __shfl_xor_sync(0xffffffffu, s, o);
    float inv = 1.f / fmaxf(s, 1.f);
    rp[lane] = v0 * inv; rp[lane + 32] = v1 * inv;
}

// ===== merged weight-split prep (verbatim R14/R16) ===========================
#define W1_ELEMS   (LOUT*256*256)
#define CV_ELEMS   (256*1024)
#define SG_ELEMS   (2*(128+256+256+256)*256)
#define PREP_TOTAL (W1_ELEMS + CV_ELEMS + SG_ELEMS)

__global__ void prep_split(
    const float* __restrict__ wl0, const float* __restrict__ wr0,
    const float* __restrict__ wl1, const float* __restrict__ wr1,
    const float* __restrict__ wl2, const float* __restrict__ wr2,
    const float* __restrict__ wl3, const float* __restrict__ wr3,
    const float* __restrict__ convw, const float* __restrict__ l1w,
    __half* __restrict__ pw0, __half* __restrict__ pw1,
    __nv_bfloat16* __restrict__ pc0, __nv_bfloat16* __restrict__ pc1,
    __nv_bfloat16* __restrict__ pl0, __nv_bfloat16* __restrict__ pl1)
{
    int idx = blockIdx.x * 256 + threadIdx.x;
    if (idx >= PREP_TOTAL) return;
    if (idx < W1_ELEMS) {
        int ts = idx >> 16;
        int rem = idx & 65535;
        int n = rem >> 8, o = rem & 255;
        float v = l1w[((size_t)(o * LOUT + ts)) * 256 + n];
        __nv_bfloat16 h0 = __float2bfloat16(v);
        pl0[idx] = h0;
        pl1[idx] = __float2bfloat16(v - __bfloat162float(h0));
    } else if (idx < W1_ELEMS + CV_ELEMS) {
        int i2 = idx - W1_ELEMS;
        int o = i2 >> 10, k = i2 & 1023;
        int s = k >> 8, i = k & 255;
        float v = convw[((size_t)(o * 256 + i)) * 4 + s];
        __nv_bfloat16 h0 = __float2bfloat16(v);
        pc0[i2] = h0;
        pc1[i2] = __float2bfloat16(v - __bfloat162float(h0));
    } else {
        int i2 = idx - (W1_ELEMS + CV_ELEMS);
        int mat, off, K;
        if (i2 < 65536) { mat = i2 >> 15; off = i2 & 32767; K = 128; }
        else {
            int j = i2 - 65536;
            mat = 2 + (j >> 16); off = j & 65535; K = 256;
        }
        const float* src;
        switch (mat) {
            case 0: src = wl0; break;
            case 1: src = wr0; break;
            case 2: src = wl1; break;
            case 3: src = wr1; break;
            case 4: src = wl2; break;
            case 5: src = wr2; break;
            case 6: src = wl3; break;
            default: src = wr3; break;
        }
        int k = off >> 8, n = off & 255;
        H2S s = h2_split(src[off]);
        size_t d = (size_t)mat * (HH * HH) + (size_t)n * K + k;
        pw0[d] = s.x; pw1[d] = s.y;
    }
}

// ------------- SortPool (verbatim) -------------------------------------------
__global__ __launch_bounds__(256) void sort_topk2(
    const float* __restrict__ H,
    __nv_bfloat16* __restrict__ t0, __nv_bfloat16* __restrict__ t1)
{
    int g = blockIdx.x, t = threadIdx.x;
    __shared__ float keys[64];
    __shared__ int   sel[KSORT];
    if (t < 64) keys[t] = H[((size_t)(g * 64 + t)) * HH + 255];
    __syncthreads();
    if (t < 64) {
        float kv = keys[t];
        int r = 0;
        #pragma unroll
        for (int m = 0; m < 64; m++) {
            float km = keys[m];
            r += (km > kv) || (km == kv && m < t);
        }
        if (r < KSORT) sel[r] = t;
    }
    __syncthreads();
    for (int idx = t; idx < KSORT * HH; idx += 256) {
        int r = idx >> 8, c = idx & 255;
        float v = H[((size_t)(g * 64 + sel[r])) * HH + c];
        __nv_bfloat16 h0 = __float2bfloat16(v);
        size_t d = (size_t)g * KSORT * HH + idx;
        t0[d] = h0;
        t1[d] = __float2bfloat16(v - __bfloat162float(h0));
    }
}

// ============ conv1d TC GEMM, split-K=2 (verbatim R16) =======================
#define CPROW_B   80
#define CPLANE_B  (128*CPROW_B)
#define CSTAGE_B  (4*CPLANE_B)
#define CSMZ      (2*CSTAGE_B)

__global__ __launch_bounds__(256) void conv_tc_part(
    const __nv_bfloat16* __restrict__ T0, const __nv_bfloat16* __restrict__ T1,
    const __nv_bfloat16* __restrict__ W0, const __nv_bfloat16* __restrict__ W1,
    float* __restrict__ Yp0, float* __restrict__ Yp1)
{
    extern __shared__ char smem[];
    const int t    = threadIdx.x;
    const int lane = t & 31;
    const int wid  = t >> 5;
    const int wm   = wid & 3;
    const int wn   = wid >> 2;
    const int m0   = blockIdx.y * 128;
    const int n0   = blockIdx.x * 128;
    const int kb   = blockIdx.z * 16;
    const int lr   = lane >> 2;
    const int lc   = lane & 3;
    const int nch  = 16;

    float* Yp = blockIdx.z ? Yp1 : Yp0;

    uint32_t sbase = smem_u32(smem);

    auto ld_stage = [&](int stage, int c) {
        uint32_t sb = sbase + stage * CSTAGE_B;
        int kt = (kb + c) << 5;
        int sp = kt >> 8, ko = kt & 255;
        #pragma unroll
        for (int i = 0; i < 8; i++) {
            int idx = t + i * 256;
            int pl  = idx >> 9;
            int rem = idx & 511;
            int row = rem >> 2, q = rem & 3;
            uint32_t dst = sb + pl * CPLANE_B + row * CPROW_B + q * 16;
            const __nv_bfloat16* src;
            if (pl < 2) {
                const __nv_bfloat16* P = (pl == 0) ? T0 : T1;
                int m = m0 + row;
                int g = m / 27, tp = m - g * 27;
                src = P + (size_t)((g * 30 + tp + sp) * 256 + ko) + q * 8;
            } else {
                const __nv_bfloat16* P = (pl == 2) ? W0 : W1;
                src = P + (size_t)(n0 + row) * 1024 + kt + q * 8;
            }
            cpasync16(dst, src);
        }
        asm volatile("cp.async.commit_group;" ::: "memory");
    };

    float acc[2][8][4];
    #pragma unroll
    for (int m = 0; m < 2; m++)
        #pragma unroll
        for (int j = 0; j < 8; j++)
            #pragma unroll
            for (int q = 0; q < 4; q++) acc[m][j][q] = 0.f;

    ld_stage(0, 0);
    ld_stage(1, 1);

    for (int c = 0; c < nch; c++) {
        if (c + 1 < nch) asm volatile("cp.async.wait_group 1;" ::: "memory");
        else             asm volatile("cp.async.wait_group 0;" ::: "memory");
        __syncthreads();

        const char* sb = smem + (c & 1) * CSTAGE_B;

        #pragma unroll
        for (int s = 0; s < 2; s++) {
            int kc = s * 32 + lc * 4;
            uint32_t A0f[2][4], A1f[2][4];
            #pragma unroll
            for (int m = 0; m < 2; m++) {
                int r0 = (wm * 32 + m * 16 + lr) * CPROW_B;
                int r1 = r0 + 8 * CPROW_B;
                A0f[m][0] = *(const uint32_t*)(sb + r0 + kc);
                A0f[m][1] = *(const uint32_t*)(sb + r1 + kc);
                A0f[m][2] = *(const uint32_t*)(sb + r0 + kc + 16);
                A0f[m][3] = *(const uint32_t*)(sb + r1 + kc + 16);
                A1f[m][0] = *(const uint32_t*)(sb + CPLANE_B + r0 + kc);
                A1f[m][1] = *(const uint32_t*)(sb + CPLANE_B + r1 + kc);
                A1f[m][2] = *(const uint32_t*)(sb + CPLANE_B + r0 + kc + 16);
                A1f[m][3] = *(const uint32_t*)(sb + CPLANE_B + r1 + kc + 16);
            }
            #pragma unroll
            for (int j = 0; j < 8; j++) {
                int nr = (wn * 64 + j * 8 + lr) * CPROW_B;
                uint32_t b00 = *(const uint32_t*)(sb + 2*CPLANE_B + nr + kc);
                uint32_t b01 = *(const uint32_t*)(sb + 2*CPLANE_B + nr + kc + 16);
                uint32_t b10 = *(const uint32_t*)(sb + 3*CPLANE_B + nr + kc);
                uint32_t b11 = *(const uint32_t*)(sb + 3*CPLANE_B + nr + kc + 16);
                #pragma unroll
                for (int m = 0; m < 2; m++)
                    mma16bf(acc[m][j], A0f[m][0], A0f[m][1], A0f[m][2], A0f[m][3], b00, b01);
                #pragma unroll
                for (int m = 0; m < 2; m++)
                    mma16bf(acc[m][j], A0f[m][0], A0f[m][1], A0f[m][2], A0f[m][3], b10, b11);
                #pragma unroll
                for (int m = 0; m < 2; m++)
                    mma16bf(acc[m][j], A1f[m][0], A1f[m][1], A1f[m][2], A1f[m][3], b00, b01);
            }
        }
        if (c + 2 < nch) {
            __syncthreads();
            ld_stage(c & 1, c + 2);
        }
    }

    #pragma unroll
    for (int m = 0; m < 2; m++) {
        int row = m0 + wm * 32 + m * 16 + lr;
        #pragma unroll
        for (int j = 0; j < 8; j++) {
            int col = n0 + wn * 64 + j * 8 + 2 * lc;
            *(float2*)(Yp + (size_t)row * 256 + col) =
                make_float2(acc[m][j][0], acc[m][j][1]);
            *(float2*)(Yp + (size_t)(row + 8) * 256 + col) =
                make_float2(acc[m][j][2], acc[m][j][3]);
        }
    }
}

__global__ void conv_fin(const float* __restrict__ P0, const float* __restrict__ P1,
                         const float* __restrict__ bias,
                         __nv_bfloat16* __restrict__ Y0, __nv_bfloat16* __restrict__ Y1)
{
    int i = blockIdx.x * 256 + threadIdx.x;
    if (i >= MCONV * HH) return;
    float v = fmaxf(P0[i] + P1[i] + bias[i & 255], 0.f);
    __nv_bfloat162 s = bf2_split(v);
    Y0[i] = s.x; Y1[i] = s.y;
}

// ============ lin1 TC GEMM (verbatim R14/R16) ================================
__global__ __launch_bounds__(256) void lin1_tc(
    const __nv_bfloat16* __restrict__ Y0, const __nv_bfloat16* __restrict__ Y1,
    const __nv_bfloat16* __restrict__ P0, const __nv_bfloat16* __restrict__ P1,
    float* __restrict__ Z)
{
    extern __shared__ char smem[];
    const int t    = threadIdx.x;
    const int lane = t & 31;
    const int wid  = t >> 5;
    const int wm   = wid & 3;
    const int wn   = wid >> 2;
    const int m0   = blockIdx.y * 128;
    const int n0   = blockIdx.x * 128;
    const int ts   = blockIdx.z;
    const int lr   = lane >> 2;
    const int lc   = lane & 3;
    const int nch  = 8;

    uint32_t sbase = smem_u32(smem);

    auto ld_stage = [&](int stage, int c) {
        uint32_t sb = sbase + stage * CSTAGE_B;
        int kt = c << 5;
        #pragma unroll
        for (int i = 0; i < 8; i++) {
            int idx = t + i * 256;
            int pl  = idx >> 9;
            int rem = idx & 511;
            int row = rem >> 2, q = rem & 3;
            uint32_t dst = sb + pl * CPLANE_B + row * CPROW_B + q * 16;
            const __nv_bfloat16* src;
            if (pl < 2) {
                const __nv_bfloat16* P = (pl == 0) ? Y0 : Y1;
                src = P + ((size_t)((m0 + row) * LOUT + ts)) * 256 + kt + q * 8;
            } else {
                const __nv_bfloat16* P = (pl == 2) ? P0 : P1;
                src = P + ((size_t)(ts * 256 + n0 + row)) * 256 + kt + q * 8;
            }
            cpasync16(dst, src);
        }
        asm volatile("cp.async.commit_group;" ::: "memory");
    };

    float acc[2][8][4];
    #pragma unroll
    for (int m = 0; m < 2; m++)
        #pragma unroll
        for (int j = 0; j < 8; j++)
            #pragma unroll
            for (int q = 0; q < 4; q++) acc[m][j][q] = 0.f;

    ld_stage(0, 0);
    ld_stage(1, 1);

    for (int c = 0; c < nch; c++) {
        if (c + 1 < nch) asm volatile("cp.async.wait_group 1;" ::: "memory");
        else             asm volatile("cp.async.wait_group 0;" ::: "memory");
        __syncthreads();

        const char* sb = smem + (c & 1) * CSTAGE_B;

        #pragma unroll
        for (int s = 0; s < 2; s++) {
            int kc = s * 32 + lc * 4;
            uint32_t A0f[2][4], A1f[2][4];
            #pragma unroll
            for (int m = 0; m < 2; m++) {
                int r0 = (wm * 32 + m * 16 + lr) * CPROW_B;
                int r1 = r0 + 8 * CPROW_B;
                A0f[m][0] = *(const uint32_t*)(sb + r0 + kc);
                A0f[m][1] = *(const uint32_t*)(sb + r1 + kc);
                A0f[m][2] = *(const uint32_t*)(sb + r0 + kc + 16);
                A0f[m][3] = *(const uint32_t*)(sb + r1 + kc + 16);
                A1f[m][0] = *(const uint32_t*)(sb + CPLANE_B + r0 + kc);
                A1f[m][1] = *(const uint32_t*)(sb + CPLANE_B + r1 + kc);
                A1f[m][2] = *(const uint32_t*)(sb + CPLANE_B + r0 + kc + 16);
                A1f[m][3] = *(const uint32_t*)(sb + CPLANE_B + r1 + kc + 16);
            }
            #pragma unroll
            for (int j = 0; j < 8; j++) {
                int nr = (wn * 64 + j * 8 + lr) * CPROW_B;
                uint32_t b00 = *(const uint32_t*)(sb + 2*CPLANE_B + nr + kc);
                uint32_t b01 = *(const uint32_t*)(sb + 2*CPLANE_B + nr + kc + 16);
                uint32_t b10 = *(const uint32_t*)(sb + 3*CPLANE_B + nr + kc);
                uint32_t b11 = *(const uint32_t*)(sb + 3*CPLANE_B + nr + kc + 16);
                #pragma unroll
                for (int m = 0; m < 2; m++)
                    mma16bf(acc[m][j], A0f[m][0], A0f[m][1], A0f[m][2], A0f[m][3], b00, b01);
                #pragma unroll
                for (int m = 0; m < 2; m++)
                    mma16bf(acc[m][j], A0f[m][0], A0f[m][1], A0f[m][2], A0f[m][3], b10, b11);
                #pragma unroll
                for (int m = 0; m < 2; m++)
                    mma16bf(acc[m][j], A1f[m][0], A1f[m][1], A1f[m][2], A1f[m][3], b00, b01);
            }
        }
        if (c + 2 < nch) {
            __syncthreads();
            ld_stage(c & 1, c + 2);
        }
    }

    #pragma unroll
    for (int m = 0; m < 2; m++) {
        int g = m0 + wm * 32 + m * 16 + lr;
        #pragma unroll
        for (int j = 0; j < 8; j++) {
            int col = n0 + wn * 64 + j * 8 + 2 * lc;
            atomicAdd(&Z[(size_t)g * 256 + col],           acc[m][j][0]);
            atomicAdd(&Z[(size_t)g * 256 + col + 1],       acc[m][j][1]);
            atomicAdd(&Z[(size_t)(g + 8) * 256 + col],     acc[m][j][2]);
            atomicAdd(&Z[(size_t)(g + 8) * 256 + col + 1], acc[m][j][3]);
        }
    }
}

// ------------- final MLP (verbatim) ------------------------------------------
__global__ __launch_bounds__(256) void mlp_kernel(
    const float* __restrict__ z1acc, const float* __restrict__ b1,
    const float* __restrict__ W2,   const float* __restrict__ b2,
    const float* __restrict__ W3,   const float* __restrict__ b3,
    float* __restrict__ out)
{
    int g = blockIdx.x, t = threadIdx.x;
    __shared__ float s1[256];
    __shared__ float s2[128];
    s1[t] = fmaxf(z1acc[(size_t)g * 256 + t] + b1[t], 0.f);
    __syncthreads();
    if (t < 128) {
        float acc = b2[t];
        #pragma unroll 8
        for (int k = 0; k < 256; k++) acc += s1[k] * W2[(size_t)k * 128 + t];
        s2[t] = fmaxf(acc, 0.f);
    }
    __syncthreads();
    if (t < 10) {
        float acc = b3[t];
        #pragma unroll
        for (int k = 0; k < 128; k++) acc += s2[k] * W3[(size_t)k * 10 + t];
        out[(size_t)g * 10 + t] = fmaxf(acc, 0.f);
    }
}

// ---------------- launch ----------------
extern "C" void kernel_launch(void* const* d_in, const int* in_sizes, int n_in,
                              void* d_out, int out_size)
{
    const float* x  = (const float*)d_in[0];
    const int*   ei = (const int*)  d_in[1];
    int E = in_sizes[1] / 2;
    const int* src = ei;
    const int* dst = ei + E;

    const float* wl[4] = {(const float*)d_in[3], (const float*)d_in[6],
                          (const float*)d_in[9], (const float*)d_in[12]};
    const float* wr[4] = {(const float*)d_in[4], (const float*)d_in[7],
                          (const float*)d_in[10], (const float*)d_in[13]};
    const float* sb[4] = {(const float*)d_in[5], (const float*)d_in[8],
                          (const float*)d_in[11], (const float*)d_in[14]};
    const float* convw = (const float*)d_in[15];
    const float* convb = (const float*)d_in[16];
    const float* l1w   = (const float*)d_in[17];
    const float* l1b   = (const float*)d_in[18];
    const float* l2w   = (const float*)d_in[19];
    const float* l2b   = (const float*)d_in[20];
    const float* ow    = (const float*)d_in[21];
    const float* ob    = (const float*)d_in[22];

    float *pA, *pH, *pZ1, *pYp0, *pYp1;
    __half *pa0, *pa1, *pb0, *pb1, *pw0, *pw1;
    __nv_bfloat16 *pt0, *pt1, *pc0, *pc1, *py0, *py1, *pl0, *pl1;
    cudaGetSymbolAddress((void**)&pA,   g_A);
    cudaGetSymbolAddress((void**)&pH,   g_H);
    cudaGetSymbolAddress((void**)&pZ1,  g_z1);
    cudaGetSymbolAddress((void**)&pYp0, g_yp0);
    cudaGetSymbolAddress((void**)&pYp1, g_yp1);
    cudaGetSymbolAddress((void**)&pa0, g_a0);
    cudaGetSymbolAddress((void**)&pa1, g_a1);
    cudaGetSymbolAddress((void**)&pb0, g_b0);
    cudaGetSymbolAddress((void**)&pb1, g_b1);
    cudaGetSymbolAddress((void**)&pw0, g_w0);
    cudaGetSymbolAddress((void**)&pw1, g_w1);
    cudaGetSymbolAddress((void**)&pt0, g_t0);
    cudaGetSymbolAddress((void**)&pt1, g_t1);
    cudaGetSymbolAddress((void**)&pc0, g_c0);
    cudaGetSymbolAddress((void**)&pc1, g_c1);
    cudaGetSymbolAddress((void**)&py0, g_y0);
    cudaGetSymbolAddress((void**)&py1, g_y1);
    cudaGetSymbolAddress((void**)&pl0, g_l0);
    cudaGetSymbolAddress((void**)&pl1, g_l1);

    cudaFuncSetAttribute(sage_fused, cudaFuncAttributeMaxDynamicSharedMemorySize, GSMZ);
    cudaFuncSetAttribute(conv_tc_part, cudaFuncAttributeMaxDynamicSharedMemorySize, CSMZ);
    cudaFuncSetAttribute(lin1_tc, cudaFuncAttributeMaxDynamicSharedMemorySize, CSMZ);

    // preprocessing
    zero_f<<<(NB*PP*PP + 255)/256, 256>>>(pA, NB*PP*PP);
    build_adj<<<(E + 255)/256, 256>>>(src, dst, E, pA);
    norm_adj<<<NN/8, 256>>>(pA);
    nan_split2h<<<(NN*FF + 255)/256, 256>>>(x, pa0, pa1, NN*FF);
    zero_f<<<(NB*HH + 255)/256, 256>>>(pZ1, NB*HH);
    prep_split<<<(PREP_TOTAL + 255)/256, 256>>>(
        wl[0], wr[0], wl[1], wr[1], wl[2], wr[2], wl[3], wr[3],
        convw, l1w, pw0, pw1, pc0, pc1, pl0, pl1);

    // 4 SAGE layers — fused GEMM(L,R)+combine per layer (R14-exact numerics)
    __half *i0 = pa0, *i1 = pa1;
    __half *o0 = pb0, *o1 = pb1;
    for (int l = 0; l < 4; l++) {
        int K = (l == 0) ? FF : HH;
        size_t f0 = (size_t)(2*l)   * HH * HH;
        size_t f1 = (size_t)(2*l+1) * HH * HH;
        int last = (l == 3);
        sage_fused<<<dim3(8, NN/128), 256, GSMZ>>>(
            i0, i1,
            pw0+f0, pw1+f0,
            pw0+f1, pw1+f1,
            sb[l], pH, o0, o1, pA, K, last, !last);
        __half* tmp;
        tmp = i0; i0 = o0; o0 = tmp;
        tmp = i1; i1 = o1; o1 = tmp;
    }

    // SortPool -> conv1d TC (split-K=2) -> finish -> lin1 TC -> MLP
    sort_topk2<<<NB, 256>>>(pH, pt0, pt1);
    conv_tc_part<<<dim3(2, MCONV/128, 2), 256, CSMZ>>>(pt0, pt1, pc0, pc1, pYp0, pYp1);
    conv_fin<<<(MCONV*HH + 255)/256, 256>>>(pYp0, pYp1, convb, py0, py1);
    lin1_tc<<<dim3(2, 4, LOUT), 256, CSMZ>>>(py0, py1, pl0, pl1, pZ1);
    mlp_kernel<<<NB, 256>>>(pZ1, l1b, l2w, l2b, ow, ob, (float*)d_out);
}